// round 1
// baseline (speedup 1.0000x reference)
#include <cuda_runtime.h>
#include <math.h>

#define BATCH 256
#define NPTS  1024

// Scratch (device globals — allocation-free contract)
__device__ float g_H2[33554432];       // [B*N, 128] = 128 MB
__device__ float g_G[BATCH * 1024];    // global feature
__device__ float g_Z1[BATCH * 512];
__device__ float g_Z2[BATCH * 256];
__device__ float g_RAW[BATCH * 9];

extern __shared__ float dynsmem[];

// ---------------------------------------------------------------------------
// K1: per-point MLP 3 -> 64 -> 128 (ReLU both), writes g_H2[p][128]
// 1024 blocks x 256 threads, one point per thread.
// ---------------------------------------------------------------------------
__global__ void k1_point_mlp(const float* __restrict__ x,
                             const float* __restrict__ W1, const float* __restrict__ b1,
                             const float* __restrict__ W2, const float* __restrict__ b2)
{
    float* W1s = dynsmem;          // 192
    float* b1s = W1s + 192;        // 64
    float* b2s = b1s + 64;         // 128
    float* W2s = b2s + 128;        // 64*128 = 8192
    float* h1s = W2s + 8192;       // 64*256 = 16384  (h1s[k*256 + tid])
    const int tid = threadIdx.x;

    for (int i = tid; i < 192; i += 256)  W1s[i] = W1[i];
    if (tid < 64)  b1s[tid] = b1[tid];
    if (tid < 128) b2s[tid] = b2[tid];
    for (int i = tid; i < 8192; i += 256) W2s[i] = W2[i];
    __syncthreads();

    const int p = blockIdx.x * 256 + tid;
    const float x0 = x[p * 3 + 0];
    const float x1 = x[p * 3 + 1];
    const float x2 = x[p * 3 + 2];

    #pragma unroll 8
    for (int k = 0; k < 64; ++k) {
        float h = fmaf(x0, W1s[k], fmaf(x1, W1s[64 + k], fmaf(x2, W1s[128 + k], b1s[k])));
        h1s[k * 256 + tid] = fmaxf(h, 0.0f);
    }
    // No sync needed: each thread reads only its own h1 column.

    float* outp = g_H2 + (size_t)p * 128;
    for (int j0 = 0; j0 < 128; j0 += 16) {
        float4 acc0 = *(const float4*)(b2s + j0);
        float4 acc1 = *(const float4*)(b2s + j0 + 4);
        float4 acc2 = *(const float4*)(b2s + j0 + 8);
        float4 acc3 = *(const float4*)(b2s + j0 + 12);
        #pragma unroll 8
        for (int k = 0; k < 64; ++k) {
            const float a = h1s[k * 256 + tid];
            const float4 w0 = *(const float4*)(W2s + k * 128 + j0);
            const float4 w1 = *(const float4*)(W2s + k * 128 + j0 + 4);
            const float4 w2 = *(const float4*)(W2s + k * 128 + j0 + 8);
            const float4 w3 = *(const float4*)(W2s + k * 128 + j0 + 12);
            acc0.x = fmaf(a, w0.x, acc0.x); acc0.y = fmaf(a, w0.y, acc0.y);
            acc0.z = fmaf(a, w0.z, acc0.z); acc0.w = fmaf(a, w0.w, acc0.w);
            acc1.x = fmaf(a, w1.x, acc1.x); acc1.y = fmaf(a, w1.y, acc1.y);
            acc1.z = fmaf(a, w1.z, acc1.z); acc1.w = fmaf(a, w1.w, acc1.w);
            acc2.x = fmaf(a, w2.x, acc2.x); acc2.y = fmaf(a, w2.y, acc2.y);
            acc2.z = fmaf(a, w2.z, acc2.z); acc2.w = fmaf(a, w2.w, acc2.w);
            acc3.x = fmaf(a, w3.x, acc3.x); acc3.y = fmaf(a, w3.y, acc3.y);
            acc3.z = fmaf(a, w3.z, acc3.z); acc3.w = fmaf(a, w3.w, acc3.w);
        }
        acc0.x = fmaxf(acc0.x, 0.f); acc0.y = fmaxf(acc0.y, 0.f); acc0.z = fmaxf(acc0.z, 0.f); acc0.w = fmaxf(acc0.w, 0.f);
        acc1.x = fmaxf(acc1.x, 0.f); acc1.y = fmaxf(acc1.y, 0.f); acc1.z = fmaxf(acc1.z, 0.f); acc1.w = fmaxf(acc1.w, 0.f);
        acc2.x = fmaxf(acc2.x, 0.f); acc2.y = fmaxf(acc2.y, 0.f); acc2.z = fmaxf(acc2.z, 0.f); acc2.w = fmaxf(acc2.w, 0.f);
        acc3.x = fmaxf(acc3.x, 0.f); acc3.y = fmaxf(acc3.y, 0.f); acc3.z = fmaxf(acc3.z, 0.f); acc3.w = fmaxf(acc3.w, 0.f);
        *(float4*)(outp + j0)      = acc0;
        *(float4*)(outp + j0 + 4)  = acc1;
        *(float4*)(outp + j0 + 8)  = acc2;
        *(float4*)(outp + j0 + 12) = acc3;
    }
}

// ---------------------------------------------------------------------------
// K2: fused GEMM + max-pool.
// Block = (batch b, 128-col tile). W3 tile [128k x 128c] resident in smem.
// Stream 16 tiles of 64 points; per thread: 4 points x 8 cols registers;
// fold relu(acc + b3) into running per-column max.
// ---------------------------------------------------------------------------
__global__ void k2_gemm_max(const float* __restrict__ W3, const float* __restrict__ b3)
{
    float* W3s = dynsmem;              // 128*128 = 16384 floats
    float* H2s = dynsmem + 16384;      // 64 * 132 (padded) = 8448 floats
    const int tid = threadIdx.x;
    const int b = blockIdx.x;
    const int colBase = blockIdx.y * 128;

    for (int i = tid; i < 16384; i += 256) {
        int k = i >> 7, c = i & 127;
        W3s[i] = W3[k * 1024 + colBase + c];
    }

    const int tx = tid & 15;       // 16 col groups
    const int ty = tid >> 4;       // 16 point groups of 4

    float b3r[8], cmax[8];
    #pragma unroll
    for (int c = 0; c < 8; ++c) {
        int col = (c < 4) ? (tx * 4 + c) : (64 + tx * 4 + (c - 4));
        b3r[c] = b3[colBase + col];
        cmax[c] = 0.0f;   // relu output >= 0, so 0 is a valid identity
    }

    const float* H2g = g_H2 + (size_t)b * (NPTS * 128);

    for (int pt = 0; pt < 16; ++pt) {
        __syncthreads();
        const float* src = H2g + pt * 64 * 128;
        for (int i = tid * 4; i < 64 * 128; i += 1024) {
            int p = i >> 7, k = i & 127;
            *(float4*)(H2s + p * 132 + k) = *(const float4*)(src + i);
        }
        __syncthreads();

        float acc[4][8];
        #pragma unroll
        for (int p = 0; p < 4; ++p)
            #pragma unroll
            for (int c = 0; c < 8; ++c) acc[p][c] = 0.0f;

        #pragma unroll 8
        for (int k = 0; k < 128; ++k) {
            const float4 w0 = *(const float4*)(W3s + k * 128 + tx * 4);
            const float4 w1 = *(const float4*)(W3s + k * 128 + 64 + tx * 4);
            const float a0 = H2s[(ty * 4 + 0) * 132 + k];
            const float a1 = H2s[(ty * 4 + 1) * 132 + k];
            const float a2 = H2s[(ty * 4 + 2) * 132 + k];
            const float a3 = H2s[(ty * 4 + 3) * 132 + k];
            acc[0][0] = fmaf(a0, w0.x, acc[0][0]); acc[0][1] = fmaf(a0, w0.y, acc[0][1]);
            acc[0][2] = fmaf(a0, w0.z, acc[0][2]); acc[0][3] = fmaf(a0, w0.w, acc[0][3]);
            acc[0][4] = fmaf(a0, w1.x, acc[0][4]); acc[0][5] = fmaf(a0, w1.y, acc[0][5]);
            acc[0][6] = fmaf(a0, w1.z, acc[0][6]); acc[0][7] = fmaf(a0, w1.w, acc[0][7]);
            acc[1][0] = fmaf(a1, w0.x, acc[1][0]); acc[1][1] = fmaf(a1, w0.y, acc[1][1]);
            acc[1][2] = fmaf(a1, w0.z, acc[1][2]); acc[1][3] = fmaf(a1, w0.w, acc[1][3]);
            acc[1][4] = fmaf(a1, w1.x, acc[1][4]); acc[1][5] = fmaf(a1, w1.y, acc[1][5]);
            acc[1][6] = fmaf(a1, w1.z, acc[1][6]); acc[1][7] = fmaf(a1, w1.w, acc[1][7]);
            acc[2][0] = fmaf(a2, w0.x, acc[2][0]); acc[2][1] = fmaf(a2, w0.y, acc[2][1]);
            acc[2][2] = fmaf(a2, w0.z, acc[2][2]); acc[2][3] = fmaf(a2, w0.w, acc[2][3]);
            acc[2][4] = fmaf(a2, w1.x, acc[2][4]); acc[2][5] = fmaf(a2, w1.y, acc[2][5]);
            acc[2][6] = fmaf(a2, w1.z, acc[2][6]); acc[2][7] = fmaf(a2, w1.w, acc[2][7]);
            acc[3][0] = fmaf(a3, w0.x, acc[3][0]); acc[3][1] = fmaf(a3, w0.y, acc[3][1]);
            acc[3][2] = fmaf(a3, w0.z, acc[3][2]); acc[3][3] = fmaf(a3, w0.w, acc[3][3]);
            acc[3][4] = fmaf(a3, w1.x, acc[3][4]); acc[3][5] = fmaf(a3, w1.y, acc[3][5]);
            acc[3][6] = fmaf(a3, w1.z, acc[3][6]); acc[3][7] = fmaf(a3, w1.w, acc[3][7]);
        }

        #pragma unroll
        for (int p = 0; p < 4; ++p)
            #pragma unroll
            for (int c = 0; c < 8; ++c)
                cmax[c] = fmaxf(cmax[c], fmaxf(acc[p][c] + b3r[c], 0.0f));
    }

    // Cross-ty reduction of column maxima (reuse W3s space)
    __syncthreads();
    float* red = W3s;   // [16][128]
    #pragma unroll
    for (int c = 0; c < 8; ++c) {
        int col = (c < 4) ? (tx * 4 + c) : (64 + tx * 4 + (c - 4));
        red[ty * 128 + col] = cmax[c];
    }
    __syncthreads();
    if (tid < 128) {
        float m = red[tid];
        #pragma unroll
        for (int j = 1; j < 16; ++j) m = fmaxf(m, red[j * 128 + tid]);
        g_G[b * 1024 + colBase + tid] = m;
    }
}

// ---------------------------------------------------------------------------
// Head GEMMs: C = act(A @ B + bias). 64x64 block tile, 4x4 per thread.
// ---------------------------------------------------------------------------
__device__ __forceinline__ void head_gemm_body(
    const float* __restrict__ A, const float* __restrict__ B,
    const float* __restrict__ bias, float* __restrict__ C,
    int K, int ldb, bool relu)
{
    float* As = dynsmem;             // 64 * 68
    float* Bs = dynsmem + 64 * 68;   // 64 * 64
    const int tid = threadIdx.x;
    const int tx = tid & 15, ty = tid >> 4;
    const int rowBase = blockIdx.x * 64;
    const int colBase = blockIdx.y * 64;

    float acc[4][4];
    #pragma unroll
    for (int p = 0; p < 4; ++p)
        #pragma unroll
        for (int c = 0; c < 4; ++c) acc[p][c] = 0.0f;

    for (int k0 = 0; k0 < K; k0 += 64) {
        __syncthreads();
        for (int i = tid * 4; i < 4096; i += 1024) {
            int r = i >> 6, k = i & 63;
            *(float4*)(As + r * 68 + k) = *(const float4*)(A + (size_t)(rowBase + r) * K + k0 + k);
        }
        for (int i = tid * 4; i < 4096; i += 1024) {
            int k = i >> 6, c = i & 63;
            *(float4*)(Bs + k * 64 + c) = *(const float4*)(B + (size_t)(k0 + k) * ldb + colBase + c);
        }
        __syncthreads();

        #pragma unroll 8
        for (int k = 0; k < 64; ++k) {
            const float4 w = *(const float4*)(Bs + k * 64 + tx * 4);
            const float a0 = As[(ty * 4 + 0) * 68 + k];
            const float a1 = As[(ty * 4 + 1) * 68 + k];
            const float a2 = As[(ty * 4 + 2) * 68 + k];
            const float a3 = As[(ty * 4 + 3) * 68 + k];
            acc[0][0] = fmaf(a0, w.x, acc[0][0]); acc[0][1] = fmaf(a0, w.y, acc[0][1]);
            acc[0][2] = fmaf(a0, w.z, acc[0][2]); acc[0][3] = fmaf(a0, w.w, acc[0][3]);
            acc[1][0] = fmaf(a1, w.x, acc[1][0]); acc[1][1] = fmaf(a1, w.y, acc[1][1]);
            acc[1][2] = fmaf(a1, w.z, acc[1][2]); acc[1][3] = fmaf(a1, w.w, acc[1][3]);
            acc[2][0] = fmaf(a2, w.x, acc[2][0]); acc[2][1] = fmaf(a2, w.y, acc[2][1]);
            acc[2][2] = fmaf(a2, w.z, acc[2][2]); acc[2][3] = fmaf(a2, w.w, acc[2][3]);
            acc[3][0] = fmaf(a3, w.x, acc[3][0]); acc[3][1] = fmaf(a3, w.y, acc[3][1]);
            acc[3][2] = fmaf(a3, w.z, acc[3][2]); acc[3][3] = fmaf(a3, w.w, acc[3][3]);
        }
    }

    #pragma unroll
    for (int p = 0; p < 4; ++p) {
        #pragma unroll
        for (int c = 0; c < 4; ++c) {
            float v = acc[p][c] + bias[colBase + tx * 4 + c];
            if (relu) v = fmaxf(v, 0.0f);
            C[(size_t)(rowBase + ty * 4 + p) * ldb + colBase + tx * 4 + c] = v;
        }
    }
}

__global__ void k3_head1(const float* __restrict__ Wh1, const float* __restrict__ bh1) {
    head_gemm_body(g_G, Wh1, bh1, g_Z1, 1024, 512, true);
}
__global__ void k4_head2(const float* __restrict__ Wh2, const float* __restrict__ bh2) {
    head_gemm_body(g_Z1, Wh2, bh2, g_Z2, 512, 256, true);
}

// ---------------------------------------------------------------------------
// K5: raw = Z2 @ Wh3 + bh3   ([256,256]@[256,9])
// ---------------------------------------------------------------------------
__global__ void k5_raw(const float* __restrict__ Wh3, const float* __restrict__ bh3)
{
    int i = blockIdx.x * 256 + threadIdx.x;
    if (i >= BATCH * 9) return;
    int b = i / 9, j = i % 9;
    float acc = bh3[j];
    const float* z = g_Z2 + b * 256;
    #pragma unroll 8
    for (int k = 0; k < 256; ++k) acc = fmaf(z[k], Wh3[k * 9 + j], acc);
    g_RAW[i] = acc;
}

// ---------------------------------------------------------------------------
// K6: SVD projection onto SO(3). One thread per 3x3 matrix.
// Jacobi eigendecomposition of A = M^T M gives V, then
// u1 = normalize(M v1), u2 = GS-orth(M v2), u3 = det(V) * (u1 x u2),
// R = u1 v1^T + u2 v2^T + u3 v3^T  ==  U diag(1,1,det) V^T.
// ---------------------------------------------------------------------------
__device__ __forceinline__ void jrot(float A[3][3], float V[3][3], int p, int q)
{
    float apq = A[p][q];
    if (fabsf(apq) < 1e-20f) return;
    float tau = (A[q][q] - A[p][p]) / (2.0f * apq);
    float t = copysignf(1.0f, tau) / (fabsf(tau) + sqrtf(1.0f + tau * tau));
    float c = 1.0f / sqrtf(1.0f + t * t);
    float s = t * c;
    for (int r = 0; r < 3; ++r) {           // A <- A * J
        float arp = A[r][p], arq = A[r][q];
        A[r][p] = c * arp - s * arq;
        A[r][q] = s * arp + c * arq;
    }
    for (int r = 0; r < 3; ++r) {           // A <- J^T * A
        float apr = A[p][r], aqr = A[q][r];
        A[p][r] = c * apr - s * aqr;
        A[q][r] = s * apr + c * aqr;
    }
    for (int r = 0; r < 3; ++r) {           // V <- V * J
        float vrp = V[r][p], vrq = V[r][q];
        V[r][p] = c * vrp - s * vrq;
        V[r][q] = s * vrp + c * vrq;
    }
}

__global__ void k6_svd(float* __restrict__ out)
{
    int i = blockIdx.x * 32 + threadIdx.x;
    if (i >= BATCH) return;

    float M[3][3];
    for (int r = 0; r < 3; ++r)
        for (int c = 0; c < 3; ++c)
            M[r][c] = g_RAW[i * 9 + r * 3 + c];

    float A[3][3], V[3][3];
    for (int r = 0; r < 3; ++r)
        for (int c = 0; c < 3; ++c) {
            A[r][c] = M[0][r] * M[0][c] + M[1][r] * M[1][c] + M[2][r] * M[2][c];
            V[r][c] = (r == c) ? 1.0f : 0.0f;
        }

    for (int sweep = 0; sweep < 12; ++sweep) {
        jrot(A, V, 0, 1);
        jrot(A, V, 0, 2);
        jrot(A, V, 1, 2);
    }

    // sort eigenvalues descending
    float e0 = A[0][0], e1 = A[1][1], e2 = A[2][2];
    int i0 = 0, i1 = 1, i2 = 2;
    if (e0 < e1) { float t = e0; e0 = e1; e1 = t; int ti = i0; i0 = i1; i1 = ti; }
    if (e0 < e2) { float t = e0; e0 = e2; e2 = t; int ti = i0; i0 = i2; i2 = ti; }
    if (e1 < e2) { float t = e1; e1 = e2; e2 = t; int ti = i1; i1 = i2; i2 = ti; }

    float v1[3], v2[3], v3[3];
    for (int r = 0; r < 3; ++r) { v1[r] = V[r][i0]; v2[r] = V[r][i1]; v3[r] = V[r][i2]; }

    float detV = v1[0] * (v2[1] * v3[2] - v2[2] * v3[1])
               - v1[1] * (v2[0] * v3[2] - v2[2] * v3[0])
               + v1[2] * (v2[0] * v3[1] - v2[1] * v3[0]);

    float w1[3], w2[3];
    for (int r = 0; r < 3; ++r) {
        w1[r] = M[r][0] * v1[0] + M[r][1] * v1[1] + M[r][2] * v1[2];
        w2[r] = M[r][0] * v2[0] + M[r][1] * v2[1] + M[r][2] * v2[2];
    }
    float n1 = sqrtf(w1[0] * w1[0] + w1[1] * w1[1] + w1[2] * w1[2] + 1e-30f);
    float u1[3] = { w1[0] / n1, w1[1] / n1, w1[2] / n1 };
    float d12 = u1[0] * w2[0] + u1[1] * w2[1] + u1[2] * w2[2];
    for (int r = 0; r < 3; ++r) w2[r] -= d12 * u1[r];
    float n2 = sqrtf(w2[0] * w2[0] + w2[1] * w2[1] + w2[2] * w2[2] + 1e-30f);
    float u2[3] = { w2[0] / n2, w2[1] / n2, w2[2] / n2 };
    float u3[3] = { u1[1] * u2[2] - u1[2] * u2[1],
                    u1[2] * u2[0] - u1[0] * u2[2],
                    u1[0] * u2[1] - u1[1] * u2[0] };
    if (detV < 0.0f) { u3[0] = -u3[0]; u3[1] = -u3[1]; u3[2] = -u3[2]; }

    for (int r = 0; r < 3; ++r)
        for (int c = 0; c < 3; ++c)
            out[i * 9 + r * 3 + c] = u1[r] * v1[c] + u2[r] * v2[c] + u3[r] * v3[c];
}

// ---------------------------------------------------------------------------
extern "C" void kernel_launch(void* const* d_in, const int* in_sizes, int n_in,
                              void* d_out, int out_size)
{
    const float* x   = (const float*)d_in[0];
    const float* W1  = (const float*)d_in[1];
    const float* b1  = (const float*)d_in[2];
    const float* W2  = (const float*)d_in[3];
    const float* b2  = (const float*)d_in[4];
    const float* W3  = (const float*)d_in[5];
    const float* b3  = (const float*)d_in[6];
    const float* Wh1 = (const float*)d_in[7];
    const float* bh1 = (const float*)d_in[8];
    const float* Wh2 = (const float*)d_in[9];
    const float* bh2 = (const float*)d_in[10];
    const float* Wh3 = (const float*)d_in[11];
    const float* bh3 = (const float*)d_in[12];
    float* out = (float*)d_out;

    const int smem1 = (192 + 64 + 128 + 8192 + 16384) * 4;   // 99840 B
    const int smem2 = (16384 + 64 * 132) * 4;                // 99328 B
    const int smem3 = (64 * 68 + 64 * 64) * 4;               // 33792 B

    cudaFuncSetAttribute(k1_point_mlp, cudaFuncAttributeMaxDynamicSharedMemorySize, smem1);
    cudaFuncSetAttribute(k2_gemm_max,  cudaFuncAttributeMaxDynamicSharedMemorySize, smem2);

    k1_point_mlp<<<1024, 256, smem1>>>(x, W1, b1, W2, b2);
    k2_gemm_max<<<dim3(256, 8), 256, smem2>>>(W3, b3);
    k3_head1<<<dim3(4, 8), 256, smem3>>>(Wh1, bh1);
    k4_head2<<<dim3(4, 4), 256, smem3>>>(Wh2, bh2);
    k5_raw<<<9, 256>>>(Wh3, bh3);
    k6_svd<<<8, 32>>>(out);

    (void)in_sizes; (void)n_in; (void)out_size;
}

// round 3
// speedup vs baseline: 1.9842x; 1.9842x over previous
#include <cuda_runtime.h>
#include <cuda_bf16.h>
#include <math.h>
#include <cstdint>

#define BATCH 256
#define NPTS  1024

// Scratch (device globals — allocation-free contract)
__device__ __nv_bfloat16 g_H2hi[BATCH * NPTS * 128];   // 64 MB
__device__ __nv_bfloat16 g_H2lo[BATCH * NPTS * 128];   // 64 MB
__device__ float g_G[BATCH * 1024];
__device__ float g_Z1[BATCH * 512];
__device__ float g_Z2[BATCH * 256];
__device__ float g_RAW[BATCH * 9];

extern __shared__ char smem_raw[];

__device__ __forceinline__ uint32_t smem_u32(const void* p) {
    uint32_t a;
    asm("{ .reg .u64 t; cvta.to.shared.u64 t, %1; cvt.u32.u64 %0, t; }" : "=r"(a) : "l"(p));
    return a;
}

#define LDSM_X4(r0, r1, r2, r3, addr) \
    asm volatile("ldmatrix.sync.aligned.m8n8.x4.shared.b16 {%0,%1,%2,%3}, [%4];" \
                 : "=r"(r0), "=r"(r1), "=r"(r2), "=r"(r3) : "r"(addr))

__device__ __forceinline__ void mma_bf16(float* d, const uint32_t* a, const uint32_t* b) {
    asm volatile("mma.sync.aligned.m16n8k16.row.col.f32.bf16.bf16.f32 "
                 "{%0,%1,%2,%3},{%4,%5,%6,%7},{%8,%9},{%0,%1,%2,%3};"
                 : "+f"(d[0]), "+f"(d[1]), "+f"(d[2]), "+f"(d[3])
                 : "r"(a[0]), "r"(a[1]), "r"(a[2]), "r"(a[3]), "r"(b[0]), "r"(b[1]));
}

// ---------------------------------------------------------------------------
// K1: per-point MLP 3 -> 64 -> 128 (ReLU), writes bf16 hi/lo split of h2
// ---------------------------------------------------------------------------
__device__ __forceinline__ uint32_t bf2u(__nv_bfloat162 v) {
    uint32_t u; *(__nv_bfloat162*)&u = v; return u;
}
__device__ __forceinline__ void split8(float4 a, float4 b, uint4& hi, uint4& lo) {
    __nv_bfloat162 h0 = __floats2bfloat162_rn(a.x, a.y);
    __nv_bfloat162 h1 = __floats2bfloat162_rn(a.z, a.w);
    __nv_bfloat162 h2 = __floats2bfloat162_rn(b.x, b.y);
    __nv_bfloat162 h3 = __floats2bfloat162_rn(b.z, b.w);
    __nv_bfloat162 l0 = __floats2bfloat162_rn(a.x - __bfloat162float(h0.x), a.y - __bfloat162float(h0.y));
    __nv_bfloat162 l1 = __floats2bfloat162_rn(a.z - __bfloat162float(h1.x), a.w - __bfloat162float(h1.y));
    __nv_bfloat162 l2 = __floats2bfloat162_rn(b.x - __bfloat162float(h2.x), b.y - __bfloat162float(h2.y));
    __nv_bfloat162 l3 = __floats2bfloat162_rn(b.z - __bfloat162float(h3.x), b.w - __bfloat162float(h3.y));
    hi = make_uint4(bf2u(h0), bf2u(h1), bf2u(h2), bf2u(h3));
    lo = make_uint4(bf2u(l0), bf2u(l1), bf2u(l2), bf2u(l3));
}

__global__ void k1_point_mlp(const float* __restrict__ x,
                             const float* __restrict__ W1, const float* __restrict__ b1,
                             const float* __restrict__ W2, const float* __restrict__ b2)
{
    float* W1s = (float*)smem_raw;     // 192
    float* b1s = W1s + 192;            // 64
    float* b2s = b1s + 64;             // 128
    float* W2s = b2s + 128;            // 64*128
    float* h1s = W2s + 8192;           // 64*256
    const int tid = threadIdx.x;

    for (int i = tid; i < 192; i += 256)  W1s[i] = W1[i];
    if (tid < 64)  b1s[tid] = b1[tid];
    if (tid < 128) b2s[tid] = b2[tid];
    for (int i = tid; i < 8192; i += 256) W2s[i] = W2[i];
    __syncthreads();

    const int p = blockIdx.x * 256 + tid;
    const float x0 = x[p * 3 + 0];
    const float x1 = x[p * 3 + 1];
    const float x2 = x[p * 3 + 2];

    #pragma unroll 8
    for (int k = 0; k < 64; ++k) {
        float h = fmaf(x0, W1s[k], fmaf(x1, W1s[64 + k], fmaf(x2, W1s[128 + k], b1s[k])));
        h1s[k * 256 + tid] = fmaxf(h, 0.0f);
    }

    uint4* outHi = (uint4*)(g_H2hi + (size_t)p * 128);
    uint4* outLo = (uint4*)(g_H2lo + (size_t)p * 128);
    for (int j0 = 0; j0 < 128; j0 += 16) {
        float4 acc0 = *(const float4*)(b2s + j0);
        float4 acc1 = *(const float4*)(b2s + j0 + 4);
        float4 acc2 = *(const float4*)(b2s + j0 + 8);
        float4 acc3 = *(const float4*)(b2s + j0 + 12);
        #pragma unroll 8
        for (int k = 0; k < 64; ++k) {
            const float a = h1s[k * 256 + tid];
            const float4 w0 = *(const float4*)(W2s + k * 128 + j0);
            const float4 w1 = *(const float4*)(W2s + k * 128 + j0 + 4);
            const float4 w2 = *(const float4*)(W2s + k * 128 + j0 + 8);
            const float4 w3 = *(const float4*)(W2s + k * 128 + j0 + 12);
            acc0.x = fmaf(a, w0.x, acc0.x); acc0.y = fmaf(a, w0.y, acc0.y);
            acc0.z = fmaf(a, w0.z, acc0.z); acc0.w = fmaf(a, w0.w, acc0.w);
            acc1.x = fmaf(a, w1.x, acc1.x); acc1.y = fmaf(a, w1.y, acc1.y);
            acc1.z = fmaf(a, w1.z, acc1.z); acc1.w = fmaf(a, w1.w, acc1.w);
            acc2.x = fmaf(a, w2.x, acc2.x); acc2.y = fmaf(a, w2.y, acc2.y);
            acc2.z = fmaf(a, w2.z, acc2.z); acc2.w = fmaf(a, w2.w, acc2.w);
            acc3.x = fmaf(a, w3.x, acc3.x); acc3.y = fmaf(a, w3.y, acc3.y);
            acc3.z = fmaf(a, w3.z, acc3.z); acc3.w = fmaf(a, w3.w, acc3.w);
        }
        acc0.x = fmaxf(acc0.x, 0.f); acc0.y = fmaxf(acc0.y, 0.f); acc0.z = fmaxf(acc0.z, 0.f); acc0.w = fmaxf(acc0.w, 0.f);
        acc1.x = fmaxf(acc1.x, 0.f); acc1.y = fmaxf(acc1.y, 0.f); acc1.z = fmaxf(acc1.z, 0.f); acc1.w = fmaxf(acc1.w, 0.f);
        acc2.x = fmaxf(acc2.x, 0.f); acc2.y = fmaxf(acc2.y, 0.f); acc2.z = fmaxf(acc2.z, 0.f); acc2.w = fmaxf(acc2.w, 0.f);
        acc3.x = fmaxf(acc3.x, 0.f); acc3.y = fmaxf(acc3.y, 0.f); acc3.z = fmaxf(acc3.z, 0.f); acc3.w = fmaxf(acc3.w, 0.f);
        uint4 hiA, loA, hiB, loB;
        split8(acc0, acc1, hiA, loA);
        split8(acc2, acc3, hiB, loB);
        outHi[j0 / 8]     = hiA;
        outHi[j0 / 8 + 1] = hiB;
        outLo[j0 / 8]     = loA;
        outLo[j0 / 8 + 1] = loB;
    }
}

// ---------------------------------------------------------------------------
// K2: HMMA (mma.sync bf16) fused GEMM + max-pool.
// CTA = (batch b, 256-col group), 512 threads = 4x4 warps, warp tile 32x64.
// B = W3^T hi/lo bf16 in smem (row pad +16B -> conflict-free ldmatrix).
// 8 point-tiles of 128 rows: A hi/lo -> smem, 3 combos x 8 ksteps of HMMA,
// per-lane row-max folded across tiles; bias+relu once at the end.
// ---------------------------------------------------------------------------
#define LDP 272                      // padded row stride in bytes (128 bf16 + 16B)
#define OFF_A_HI 0
#define OFF_A_LO 34816               // 128*272
#define OFF_B_HI 69632
#define OFF_B_LO 139264              // + 256*272
#define OFF_SCR  208896              // float[4][256]
#define OFF_B3   212992              // float[256]
#define K2_SMEM  214016

__global__ void __launch_bounds__(512, 1) k2_gemm_max_mma(const float* __restrict__ W3,
                                                          const float* __restrict__ b3)
{
    char* sm = smem_raw;
    const uint32_t sb = smem_u32(sm);
    const int tid = threadIdx.x, lane = tid & 31, w = tid >> 5;
    const int wm = w & 3, wn = w >> 2;
    const int b = blockIdx.x;
    const int colBase = blockIdx.y * 256;

    float* scratch = (float*)(sm + OFF_SCR);
    float* b3s     = (float*)(sm + OFF_B3);

    // B fill: Bs[n][k] = W3[k][colBase+n] split hi/lo (once per CTA)
    for (int idx = tid; idx < 32768; idx += 512) {
        const int n = idx & 255, k = idx >> 8;
        const float v = W3[k * 1024 + colBase + n];
        const __nv_bfloat16 h = __float2bfloat16(v);
        const __nv_bfloat16 l = __float2bfloat16(v - __bfloat162float(h));
        *(__nv_bfloat16*)(sm + OFF_B_HI + n * LDP + k * 2) = h;
        *(__nv_bfloat16*)(sm + OFF_B_LO + n * LDP + k * 2) = l;
    }
    if (tid < 256) b3s[tid] = b3[colBase + tid];

    // ldmatrix per-lane addresses
    // A (x4 covering m16 x k16): row = m0 + lane%16, colByte = (lane/16)*16
    const uint32_t aRow = (uint32_t)(wm * 32 + (lane & 15));
    const uint32_t aCol = (uint32_t)((lane >> 4) * 16);
    const uint32_t aHi0 = sb + OFF_A_HI + aRow * LDP + aCol;
    const uint32_t aHi1 = aHi0 + 16 * LDP;
    const uint32_t aLo0 = sb + OFF_A_LO + aRow * LDP + aCol;
    const uint32_t aLo1 = aLo0 + 16 * LDP;
    // B (x4 covering n16 x k16): row n = n0 + (lane&7) + ((lane>>4)<<3), colByte = ((lane>>3)&1)*16
    const uint32_t bRow = (uint32_t)(wn * 64 + (lane & 7) + ((lane >> 4) << 3));
    const uint32_t bCol = (uint32_t)(((lane >> 3) & 1) * 16);
    const uint32_t bHi0 = sb + OFF_B_HI + bRow * LDP + bCol;
    const uint32_t bLo0 = sb + OFF_B_LO + bRow * LDP + bCol;

    float runmax[16];
    #pragma unroll
    for (int i = 0; i < 16; ++i) runmax[i] = -1e30f;

    const uint4* srcHi = (const uint4*)(g_H2hi + (size_t)b * NPTS * 128);
    const uint4* srcLo = (const uint4*)(g_H2lo + (size_t)b * NPTS * 128);

    for (int pt = 0; pt < 8; ++pt) {
        __syncthreads();
        // A fill: 128 rows x 16 uint4, hi+lo
        const int tb = pt * 128 * 16;
        #pragma unroll
        for (int it = 0; it < 4; ++it) {
            const int idx = tid + it * 512;
            const int m = idx >> 4, j = idx & 15;
            *(uint4*)(sm + OFF_A_HI + m * LDP + j * 16) = srcHi[tb + idx];
            *(uint4*)(sm + OFF_A_LO + m * LDP + j * 16) = srcLo[tb + idx];
        }
        __syncthreads();

        float d[2][8][4];
        #pragma unroll
        for (int mt = 0; mt < 2; ++mt)
            #pragma unroll
            for (int j = 0; j < 8; ++j)
                #pragma unroll
                for (int c = 0; c < 4; ++c) d[mt][j][c] = 0.0f;

        #pragma unroll
        for (int ks = 0; ks < 8; ++ks) {
            const uint32_t ko = ks * 32;
            uint32_t aH0[4], aH1[4], aL0[4], aL1[4];
            LDSM_X4(aH0[0], aH0[1], aH0[2], aH0[3], aHi0 + ko);
            LDSM_X4(aH1[0], aH1[1], aH1[2], aH1[3], aHi1 + ko);
            LDSM_X4(aL0[0], aL0[1], aL0[2], aL0[3], aLo0 + ko);
            LDSM_X4(aL1[0], aL1[1], aL1[2], aL1[3], aLo1 + ko);
            #pragma unroll
            for (int j = 0; j < 4; ++j) {
                uint32_t bH[4], bL[4];
                LDSM_X4(bH[0], bH[1], bH[2], bH[3], bHi0 + j * (16 * LDP) + ko);
                LDSM_X4(bL[0], bL[1], bL[2], bL[3], bLo0 + j * (16 * LDP) + ko);
                // Ah*Bh
                mma_bf16(d[0][2 * j],     aH0, bH);
                mma_bf16(d[1][2 * j],     aH1, bH);
                mma_bf16(d[0][2 * j + 1], aH0, bH + 2);
                mma_bf16(d[1][2 * j + 1], aH1, bH + 2);
                // Ah*Bl
                mma_bf16(d[0][2 * j],     aH0, bL);
                mma_bf16(d[1][2 * j],     aH1, bL);
                mma_bf16(d[0][2 * j + 1], aH0, bL + 2);
                mma_bf16(d[1][2 * j + 1], aH1, bL + 2);
                // Al*Bh
                mma_bf16(d[0][2 * j],     aL0, bH);
                mma_bf16(d[1][2 * j],     aL1, bH);
                mma_bf16(d[0][2 * j + 1], aL0, bH + 2);
                mma_bf16(d[1][2 * j + 1], aL1, bH + 2);
            }
        }

        // fold per-lane row max (rows covered by this lane: g, g+8 in both mtiles)
        #pragma unroll
        for (int j = 0; j < 8; ++j)
            #pragma unroll
            for (int c = 0; c < 2; ++c) {
                float m = fmaxf(fmaxf(d[0][j][c], d[0][j][c + 2]),
                                fmaxf(d[1][j][c], d[1][j][c + 2]));
                runmax[j * 2 + c] = fmaxf(runmax[j * 2 + c], m);
            }
    }

    // Cross-lane row reduction (lanes differing in bits 2..4 share column ids)
    #pragma unroll
    for (int i = 0; i < 16; ++i) {
        float v = runmax[i];
        v = fmaxf(v, __shfl_xor_sync(0xffffffffu, v, 4));
        v = fmaxf(v, __shfl_xor_sync(0xffffffffu, v, 8));
        v = fmaxf(v, __shfl_xor_sync(0xffffffffu, v, 16));
        runmax[i] = v;
    }
    if (lane < 4) {
        #pragma unroll
        for (int j = 0; j < 8; ++j)
            #pragma unroll
            for (int c = 0; c < 2; ++c)
                scratch[wm * 256 + wn * 64 + j * 8 + lane * 2 + c] = runmax[j * 2 + c];
    }
    __syncthreads();
    if (tid < 256) {
        float m = fmaxf(fmaxf(scratch[tid], scratch[256 + tid]),
                        fmaxf(scratch[512 + tid], scratch[768 + tid]));
        g_G[b * 1024 + colBase + tid] = fmaxf(m + b3s[tid], 0.0f);
    }
}

// ---------------------------------------------------------------------------
// Head GEMMs: C = act(A @ B + bias). 64x64 block tile, 4x4 per thread.
// ---------------------------------------------------------------------------
__device__ __forceinline__ void head_gemm_body(
    const float* __restrict__ A, const float* __restrict__ B,
    const float* __restrict__ bias, float* __restrict__ C,
    int K, int ldb, bool relu)
{
    float* As = (float*)smem_raw;    // 64 * 68
    float* Bs = As + 64 * 68;        // 64 * 64
    const int tid = threadIdx.x;
    const int tx = tid & 15, ty = tid >> 4;
    const int rowBase = blockIdx.x * 64;
    const int colBase = blockIdx.y * 64;

    float acc[4][4];
    #pragma unroll
    for (int p = 0; p < 4; ++p)
        #pragma unroll
        for (int c = 0; c < 4; ++c) acc[p][c] = 0.0f;

    for (int k0 = 0; k0 < K; k0 += 64) {
        __syncthreads();
        for (int i = tid * 4; i < 4096; i += 1024) {
            int r = i >> 6, k = i & 63;
            *(float4*)(As + r * 68 + k) = *(const float4*)(A + (size_t)(rowBase + r) * K + k0 + k);
        }
        for (int i = tid * 4; i < 4096; i += 1024) {
            int k = i >> 6, c = i & 63;
            *(float4*)(Bs + k * 64 + c) = *(const float4*)(B + (size_t)(k0 + k) * ldb + colBase + c);
        }
        __syncthreads();

        #pragma unroll 8
        for (int k = 0; k < 64; ++k) {
            const float4 w = *(const float4*)(Bs + k * 64 + tx * 4);
            const float a0 = As[(ty * 4 + 0) * 68 + k];
            const float a1 = As[(ty * 4 + 1) * 68 + k];
            const float a2 = As[(ty * 4 + 2) * 68 + k];
            const float a3 = As[(ty * 4 + 3) * 68 + k];
            acc[0][0] = fmaf(a0, w.x, acc[0][0]); acc[0][1] = fmaf(a0, w.y, acc[0][1]);
            acc[0][2] = fmaf(a0, w.z, acc[0][2]); acc[0][3] = fmaf(a0, w.w, acc[0][3]);
            acc[1][0] = fmaf(a1, w.x, acc[1][0]); acc[1][1] = fmaf(a1, w.y, acc[1][1]);
            acc[1][2] = fmaf(a1, w.z, acc[1][2]); acc[1][3] = fmaf(a1, w.w, acc[1][3]);
            acc[2][0] = fmaf(a2, w.x, acc[2][0]); acc[2][1] = fmaf(a2, w.y, acc[2][1]);
            acc[2][2] = fmaf(a2, w.z, acc[2][2]); acc[2][3] = fmaf(a2, w.w, acc[2][3]);
            acc[3][0] = fmaf(a3, w.x, acc[3][0]); acc[3][1] = fmaf(a3, w.y, acc[3][1]);
            acc[3][2] = fmaf(a3, w.z, acc[3][2]); acc[3][3] = fmaf(a3, w.w, acc[3][3]);
        }
    }

    #pragma unroll
    for (int p = 0; p < 4; ++p) {
        #pragma unroll
        for (int c = 0; c < 4; ++c) {
            float v = acc[p][c] + bias[colBase + tx * 4 + c];
            if (relu) v = fmaxf(v, 0.0f);
            C[(size_t)(rowBase + ty * 4 + p) * ldb + colBase + tx * 4 + c] = v;
        }
    }
}

__global__ void k3_head1(const float* __restrict__ Wh1, const float* __restrict__ bh1) {
    head_gemm_body(g_G, Wh1, bh1, g_Z1, 1024, 512, true);
}
__global__ void k4_head2(const float* __restrict__ Wh2, const float* __restrict__ bh2) {
    head_gemm_body(g_Z1, Wh2, bh2, g_Z2, 512, 256, true);
}

// ---------------------------------------------------------------------------
// K5: raw = Z2 @ Wh3 + bh3
// ---------------------------------------------------------------------------
__global__ void k5_raw(const float* __restrict__ Wh3, const float* __restrict__ bh3)
{
    int i = blockIdx.x * 256 + threadIdx.x;
    if (i >= BATCH * 9) return;
    int b = i / 9, j = i % 9;
    float acc = bh3[j];
    const float* z = g_Z2 + b * 256;
    #pragma unroll 8
    for (int k = 0; k < 256; ++k) acc = fmaf(z[k], Wh3[k * 9 + j], acc);
    g_RAW[i] = acc;
}

// ---------------------------------------------------------------------------
// K6: SVD projection onto SO(3). One thread per 3x3 matrix.
// ---------------------------------------------------------------------------
__device__ __forceinline__ void jrot(float A[3][3], float V[3][3], int p, int q)
{
    float apq = A[p][q];
    if (fabsf(apq) < 1e-20f) return;
    float tau = (A[q][q] - A[p][p]) / (2.0f * apq);
    float t = copysignf(1.0f, tau) / (fabsf(tau) + sqrtf(1.0f + tau * tau));
    float c = 1.0f / sqrtf(1.0f + t * t);
    float s = t * c;
    for (int r = 0; r < 3; ++r) {
        float arp = A[r][p], arq = A[r][q];
        A[r][p] = c * arp - s * arq;
        A[r][q] = s * arp + c * arq;
    }
    for (int r = 0; r < 3; ++r) {
        float apr = A[p][r], aqr = A[q][r];
        A[p][r] = c * apr - s * aqr;
        A[q][r] = s * apr + c * aqr;
    }
    for (int r = 0; r < 3; ++r) {
        float vrp = V[r][p], vrq = V[r][q];
        V[r][p] = c * vrp - s * vrq;
        V[r][q] = s * vrp + c * vrq;
    }
}

__global__ void k6_svd(float* __restrict__ out)
{
    int i = blockIdx.x * 32 + threadIdx.x;
    if (i >= BATCH) return;

    float M[3][3];
    for (int r = 0; r < 3; ++r)
        for (int c = 0; c < 3; ++c)
            M[r][c] = g_RAW[i * 9 + r * 3 + c];

    float A[3][3], V[3][3];
    for (int r = 0; r < 3; ++r)
        for (int c = 0; c < 3; ++c) {
            A[r][c] = M[0][r] * M[0][c] + M[1][r] * M[1][c] + M[2][r] * M[2][c];
            V[r][c] = (r == c) ? 1.0f : 0.0f;
        }

    for (int sweep = 0; sweep < 12; ++sweep) {
        jrot(A, V, 0, 1);
        jrot(A, V, 0, 2);
        jrot(A, V, 1, 2);
    }

    float e0 = A[0][0], e1 = A[1][1], e2 = A[2][2];
    int i0 = 0, i1 = 1, i2 = 2;
    if (e0 < e1) { float t = e0; e0 = e1; e1 = t; int ti = i0; i0 = i1; i1 = ti; }
    if (e0 < e2) { float t = e0; e0 = e2; e2 = t; int ti = i0; i0 = i2; i2 = ti; }
    if (e1 < e2) { float t = e1; e1 = e2; e2 = t; int ti = i1; i1 = i2; i2 = ti; }

    float v1[3], v2[3], v3[3];
    for (int r = 0; r < 3; ++r) { v1[r] = V[r][i0]; v2[r] = V[r][i1]; v3[r] = V[r][i2]; }

    float detV = v1[0] * (v2[1] * v3[2] - v2[2] * v3[1])
               - v1[1] * (v2[0] * v3[2] - v2[2] * v3[0])
               + v1[2] * (v2[0] * v3[1] - v2[1] * v3[0]);

    float w1[3], w2[3];
    for (int r = 0; r < 3; ++r) {
        w1[r] = M[r][0] * v1[0] + M[r][1] * v1[1] + M[r][2] * v1[2];
        w2[r] = M[r][0] * v2[0] + M[r][1] * v2[1] + M[r][2] * v2[2];
    }
    float n1 = sqrtf(w1[0] * w1[0] + w1[1] * w1[1] + w1[2] * w1[2] + 1e-30f);
    float u1[3] = { w1[0] / n1, w1[1] / n1, w1[2] / n1 };
    float d12 = u1[0] * w2[0] + u1[1] * w2[1] + u1[2] * w2[2];
    for (int r = 0; r < 3; ++r) w2[r] -= d12 * u1[r];
    float n2 = sqrtf(w2[0] * w2[0] + w2[1] * w2[1] + w2[2] * w2[2] + 1e-30f);
    float u2[3] = { w2[0] / n2, w2[1] / n2, w2[2] / n2 };
    float u3[3] = { u1[1] * u2[2] - u1[2] * u2[1],
                    u1[2] * u2[0] - u1[0] * u2[2],
                    u1[0] * u2[1] - u1[1] * u2[0] };
    if (detV < 0.0f) { u3[0] = -u3[0]; u3[1] = -u3[1]; u3[2] = -u3[2]; }

    for (int r = 0; r < 3; ++r)
        for (int c = 0; c < 3; ++c)
            out[i * 9 + r * 3 + c] = u1[r] * v1[c] + u2[r] * v2[c] + u3[r] * v3[c];
}

// ---------------------------------------------------------------------------
extern "C" void kernel_launch(void* const* d_in, const int* in_sizes, int n_in,
                              void* d_out, int out_size)
{
    const float* x   = (const float*)d_in[0];
    const float* W1  = (const float*)d_in[1];
    const float* b1  = (const float*)d_in[2];
    const float* W2  = (const float*)d_in[3];
    const float* b2  = (const float*)d_in[4];
    const float* W3  = (const float*)d_in[5];
    const float* b3  = (const float*)d_in[6];
    const float* Wh1 = (const float*)d_in[7];
    const float* bh1 = (const float*)d_in[8];
    const float* Wh2 = (const float*)d_in[9];
    const float* bh2 = (const float*)d_in[10];
    const float* Wh3 = (const float*)d_in[11];
    const float* bh3 = (const float*)d_in[12];
    float* out = (float*)d_out;

    const int smem1 = (192 + 64 + 128 + 8192 + 16384) * 4;   // 99840 B
    const int smem3 = (64 * 68 + 64 * 64) * 4;               // 33792 B

    cudaFuncSetAttribute(k1_point_mlp,    cudaFuncAttributeMaxDynamicSharedMemorySize, smem1);
    cudaFuncSetAttribute(k2_gemm_max_mma, cudaFuncAttributeMaxDynamicSharedMemorySize, K2_SMEM);

    k1_point_mlp<<<1024, 256, smem1>>>(x, W1, b1, W2, b2);
    k2_gemm_max_mma<<<dim3(256, 4), 512, K2_SMEM>>>(W3, b3);
    k3_head1<<<dim3(4, 8), 256, smem3>>>(Wh1, bh1);
    k4_head2<<<dim3(4, 4), 256, smem3>>>(Wh2, bh2);
    k5_raw<<<9, 256>>>(Wh3, bh3);
    k6_svd<<<8, 32>>>(out);

    (void)in_sizes; (void)n_in; (void)out_size;
}

// round 4
// speedup vs baseline: 2.3804x; 1.1997x over previous
#include <cuda_runtime.h>
#include <cuda_bf16.h>
#include <math.h>
#include <cstdint>

#define BATCH 256
#define NPTS  1024

// Scratch (device globals — allocation-free contract)
__device__ __nv_bfloat16 g_H2hi[BATCH * NPTS * 128];   // 64 MB
__device__ __nv_bfloat16 g_H2lo[BATCH * NPTS * 128];   // 64 MB
__device__ float g_G[BATCH * 1024];
__device__ float g_Z1[BATCH * 512];
__device__ float g_Z2[BATCH * 256];
__device__ float g_RAW[BATCH * 9];

extern __shared__ char smem_raw[];

__device__ __forceinline__ uint32_t smem_u32(const void* p) {
    uint32_t a;
    asm("{ .reg .u64 t; cvta.to.shared.u64 t, %1; cvt.u32.u64 %0, t; }" : "=r"(a) : "l"(p));
    return a;
}

#define LDSM_X4(r0, r1, r2, r3, addr) \
    asm volatile("ldmatrix.sync.aligned.m8n8.x4.shared.b16 {%0,%1,%2,%3}, [%4];" \
                 : "=r"(r0), "=r"(r1), "=r"(r2), "=r"(r3) : "r"(addr))

__device__ __forceinline__ void mma_bf16(float* d, const uint32_t* a, const uint32_t* b) {
    asm volatile("mma.sync.aligned.m16n8k16.row.col.f32.bf16.bf16.f32 "
                 "{%0,%1,%2,%3},{%4,%5,%6,%7},{%8,%9},{%0,%1,%2,%3};"
                 : "+f"(d[0]), "+f"(d[1]), "+f"(d[2]), "+f"(d[3])
                 : "r"(a[0]), "r"(a[1]), "r"(a[2]), "r"(a[3]), "r"(b[0]), "r"(b[1]));
}

__device__ __forceinline__ uint32_t bf2u(__nv_bfloat162 v) {
    uint32_t u; *(__nv_bfloat162*)&u = v; return u;
}

// ---------------------------------------------------------------------------
// K1: per-point MLP 3 -> 64 (scalar) -> 128 (HMMA, 3-combo hi/lo bf16),
// fused bias+ReLU+split epilogue, writes g_H2hi/g_H2lo.
// CTA = 128 points, 512 threads = 16 warps (4x4 warp grid, warp tile 32x32).
// ---------------------------------------------------------------------------
#define K1_LDP 144                    // 64 bf16 = 128B + 16B pad
#define K1_A_HI 0
#define K1_A_LO 18432                 // 128*144
#define K1_B_HI 36864
#define K1_B_LO 55296
#define K1_W1S  73728                 // float[192]
#define K1_B1S  74496                 // float[64]
#define K1_B2S  74752                 // float[128]
#define K1_SMEM 75264

__global__ void __launch_bounds__(512, 1) k1_point_mlp(
    const float* __restrict__ x,
    const float* __restrict__ W1, const float* __restrict__ b1,
    const float* __restrict__ W2, const float* __restrict__ b2)
{
    char* sm = smem_raw;
    const uint32_t sb = smem_u32(sm);
    const int tid = threadIdx.x, lane = tid & 31, w = tid >> 5;
    const int wm = w & 3, wn = w >> 2;
    float* W1s = (float*)(sm + K1_W1S);
    float* b1s = (float*)(sm + K1_B1S);
    float* b2s = (float*)(sm + K1_B2S);

    // Stage 1: weights -> smem. B[n][k] = W2[k][n] split hi/lo.
    for (int i = tid; i < 8192; i += 512) {
        const int n = i & 127, k = i >> 7;
        const float v = W2[k * 128 + n];
        const __nv_bfloat16 h = __float2bfloat16(v);
        const __nv_bfloat16 l = __float2bfloat16(v - __bfloat162float(h));
        *(__nv_bfloat16*)(sm + K1_B_HI + n * K1_LDP + k * 2) = h;
        *(__nv_bfloat16*)(sm + K1_B_LO + n * K1_LDP + k * 2) = l;
    }
    if (tid < 192) W1s[tid] = W1[tid];
    else if (tid >= 256 && tid < 320) b1s[tid - 256] = b1[tid - 256];
    else if (tid >= 384 && tid < 512) b2s[tid - 384] = b2[tid - 384];
    __syncthreads();

    // Stage 2: layer 1 for 128 points; thread t handles point t&127, k-slice (t>>7)*16
    {
        const int pl = tid & 127;
        const int ks = (tid >> 7) * 16;
        const int pg = blockIdx.x * 128 + pl;
        const float x0 = x[pg * 3 + 0];
        const float x1 = x[pg * 3 + 1];
        const float x2 = x[pg * 3 + 2];
        #pragma unroll
        for (int kk = 0; kk < 16; kk += 2) {
            const int k = ks + kk;
            float va = fmaxf(fmaf(x0, W1s[k],     fmaf(x1, W1s[64 + k],     fmaf(x2, W1s[128 + k],     b1s[k]))), 0.0f);
            float vb = fmaxf(fmaf(x0, W1s[k + 1], fmaf(x1, W1s[64 + k + 1], fmaf(x2, W1s[128 + k + 1], b1s[k + 1]))), 0.0f);
            __nv_bfloat162 h = __floats2bfloat162_rn(va, vb);
            __nv_bfloat162 l = __floats2bfloat162_rn(va - __bfloat162float(h.x), vb - __bfloat162float(h.y));
            *(uint32_t*)(sm + K1_A_HI + pl * K1_LDP + k * 2) = bf2u(h);
            *(uint32_t*)(sm + K1_A_LO + pl * K1_LDP + k * 2) = bf2u(l);
        }
    }
    __syncthreads();

    // Stage 3: HMMA [128,64] @ [64,128]^T (B is [n][k]) with 3 combos
    const uint32_t aRow = (uint32_t)(wm * 32 + (lane & 15));
    const uint32_t aCol = (uint32_t)((lane >> 4) * 16);
    const uint32_t aHi0 = sb + K1_A_HI + aRow * K1_LDP + aCol;
    const uint32_t aHi1 = aHi0 + 16 * K1_LDP;
    const uint32_t aLo0 = sb + K1_A_LO + aRow * K1_LDP + aCol;
    const uint32_t aLo1 = aLo0 + 16 * K1_LDP;
    const uint32_t bRow = (uint32_t)(wn * 32 + (lane & 7) + ((lane >> 4) << 3));
    const uint32_t bCol = (uint32_t)(((lane >> 3) & 1) * 16);
    const uint32_t bHi0 = sb + K1_B_HI + bRow * K1_LDP + bCol;
    const uint32_t bLo0 = sb + K1_B_LO + bRow * K1_LDP + bCol;

    float d[2][4][4];
    #pragma unroll
    for (int mt = 0; mt < 2; ++mt)
        #pragma unroll
        for (int j = 0; j < 4; ++j)
            #pragma unroll
            for (int c = 0; c < 4; ++c) d[mt][j][c] = 0.0f;

    #pragma unroll
    for (int ks = 0; ks < 4; ++ks) {
        const uint32_t ko = ks * 32;
        uint32_t aH0[4], aH1[4], aL0[4], aL1[4];
        LDSM_X4(aH0[0], aH0[1], aH0[2], aH0[3], aHi0 + ko);
        LDSM_X4(aH1[0], aH1[1], aH1[2], aH1[3], aHi1 + ko);
        LDSM_X4(aL0[0], aL0[1], aL0[2], aL0[3], aLo0 + ko);
        LDSM_X4(aL1[0], aL1[1], aL1[2], aL1[3], aLo1 + ko);
        #pragma unroll
        for (int j = 0; j < 2; ++j) {
            uint32_t bH[4], bL[4];
            LDSM_X4(bH[0], bH[1], bH[2], bH[3], bHi0 + j * (16 * K1_LDP) + ko);
            LDSM_X4(bL[0], bL[1], bL[2], bL[3], bLo0 + j * (16 * K1_LDP) + ko);
            mma_bf16(d[0][2 * j],     aH0, bH);
            mma_bf16(d[1][2 * j],     aH1, bH);
            mma_bf16(d[0][2 * j + 1], aH0, bH + 2);
            mma_bf16(d[1][2 * j + 1], aH1, bH + 2);
            mma_bf16(d[0][2 * j],     aH0, bL);
            mma_bf16(d[1][2 * j],     aH1, bL);
            mma_bf16(d[0][2 * j + 1], aH0, bL + 2);
            mma_bf16(d[1][2 * j + 1], aH1, bL + 2);
            mma_bf16(d[0][2 * j],     aL0, bH);
            mma_bf16(d[1][2 * j],     aL1, bH);
            mma_bf16(d[0][2 * j + 1], aL0, bH + 2);
            mma_bf16(d[1][2 * j + 1], aL1, bH + 2);
        }
    }

    // Epilogue: bias + relu + hi/lo split -> gmem (bf162 stores)
    const int pBase = blockIdx.x * 128;
    #pragma unroll
    for (int mt = 0; mt < 2; ++mt) {
        #pragma unroll
        for (int j = 0; j < 4; ++j) {
            const int col = wn * 32 + j * 8 + (lane & 3) * 2;
            const float bc0 = b2s[col], bc1 = b2s[col + 1];
            #pragma unroll
            for (int rr = 0; rr < 2; ++rr) {
                const int row = pBase + wm * 32 + mt * 16 + (lane >> 2) + rr * 8;
                const float v0 = fmaxf(d[mt][j][rr * 2 + 0] + bc0, 0.0f);
                const float v1 = fmaxf(d[mt][j][rr * 2 + 1] + bc1, 0.0f);
                __nv_bfloat162 h = __floats2bfloat162_rn(v0, v1);
                __nv_bfloat162 l = __floats2bfloat162_rn(v0 - __bfloat162float(h.x), v1 - __bfloat162float(h.y));
                *(uint32_t*)(g_H2hi + (size_t)row * 128 + col) = bf2u(h);
                *(uint32_t*)(g_H2lo + (size_t)row * 128 + col) = bf2u(l);
            }
        }
    }
}

// ---------------------------------------------------------------------------
// K2: HMMA (mma.sync bf16) fused GEMM + max-pool. (unchanged from R3)
// ---------------------------------------------------------------------------
#define LDP 272
#define OFF_A_HI 0
#define OFF_A_LO 34816
#define OFF_B_HI 69632
#define OFF_B_LO 139264
#define OFF_SCR  208896
#define OFF_B3   212992
#define K2_SMEM  214016

__global__ void __launch_bounds__(512, 1) k2_gemm_max_mma(const float* __restrict__ W3,
                                                          const float* __restrict__ b3)
{
    char* sm = smem_raw;
    const uint32_t sb = smem_u32(sm);
    const int tid = threadIdx.x, lane = tid & 31, w = tid >> 5;
    const int wm = w & 3, wn = w >> 2;
    const int b = blockIdx.x;
    const int colBase = blockIdx.y * 256;

    float* scratch = (float*)(sm + OFF_SCR);
    float* b3s     = (float*)(sm + OFF_B3);

    for (int idx = tid; idx < 32768; idx += 512) {
        const int n = idx & 255, k = idx >> 8;
        const float v = W3[k * 1024 + colBase + n];
        const __nv_bfloat16 h = __float2bfloat16(v);
        const __nv_bfloat16 l = __float2bfloat16(v - __bfloat162float(h));
        *(__nv_bfloat16*)(sm + OFF_B_HI + n * LDP + k * 2) = h;
        *(__nv_bfloat16*)(sm + OFF_B_LO + n * LDP + k * 2) = l;
    }
    if (tid < 256) b3s[tid] = b3[colBase + tid];

    const uint32_t aRow = (uint32_t)(wm * 32 + (lane & 15));
    const uint32_t aCol = (uint32_t)((lane >> 4) * 16);
    const uint32_t aHi0 = sb + OFF_A_HI + aRow * LDP + aCol;
    const uint32_t aHi1 = aHi0 + 16 * LDP;
    const uint32_t aLo0 = sb + OFF_A_LO + aRow * LDP + aCol;
    const uint32_t aLo1 = aLo0 + 16 * LDP;
    const uint32_t bRow = (uint32_t)(wn * 64 + (lane & 7) + ((lane >> 4) << 3));
    const uint32_t bCol = (uint32_t)(((lane >> 3) & 1) * 16);
    const uint32_t bHi0 = sb + OFF_B_HI + bRow * LDP + bCol;
    const uint32_t bLo0 = sb + OFF_B_LO + bRow * LDP + bCol;

    float runmax[16];
    #pragma unroll
    for (int i = 0; i < 16; ++i) runmax[i] = -1e30f;

    const uint4* srcHi = (const uint4*)(g_H2hi + (size_t)b * NPTS * 128);
    const uint4* srcLo = (const uint4*)(g_H2lo + (size_t)b * NPTS * 128);

    for (int pt = 0; pt < 8; ++pt) {
        __syncthreads();
        const int tb = pt * 128 * 16;
        #pragma unroll
        for (int it = 0; it < 4; ++it) {
            const int idx = tid + it * 512;
            const int m = idx >> 4, j = idx & 15;
            *(uint4*)(sm + OFF_A_HI + m * LDP + j * 16) = srcHi[tb + idx];
            *(uint4*)(sm + OFF_A_LO + m * LDP + j * 16) = srcLo[tb + idx];
        }
        __syncthreads();

        float d[2][8][4];
        #pragma unroll
        for (int mt = 0; mt < 2; ++mt)
            #pragma unroll
            for (int j = 0; j < 8; ++j)
                #pragma unroll
                for (int c = 0; c < 4; ++c) d[mt][j][c] = 0.0f;

        #pragma unroll
        for (int ks = 0; ks < 8; ++ks) {
            const uint32_t ko = ks * 32;
            uint32_t aH0[4], aH1[4], aL0[4], aL1[4];
            LDSM_X4(aH0[0], aH0[1], aH0[2], aH0[3], aHi0 + ko);
            LDSM_X4(aH1[0], aH1[1], aH1[2], aH1[3], aHi1 + ko);
            LDSM_X4(aL0[0], aL0[1], aL0[2], aL0[3], aLo0 + ko);
            LDSM_X4(aL1[0], aL1[1], aL1[2], aL1[3], aLo1 + ko);
            #pragma unroll
            for (int j = 0; j < 4; ++j) {
                uint32_t bH[4], bL[4];
                LDSM_X4(bH[0], bH[1], bH[2], bH[3], bHi0 + j * (16 * LDP) + ko);
                LDSM_X4(bL[0], bL[1], bL[2], bL[3], bLo0 + j * (16 * LDP) + ko);
                mma_bf16(d[0][2 * j],     aH0, bH);
                mma_bf16(d[1][2 * j],     aH1, bH);
                mma_bf16(d[0][2 * j + 1], aH0, bH + 2);
                mma_bf16(d[1][2 * j + 1], aH1, bH + 2);
                mma_bf16(d[0][2 * j],     aH0, bL);
                mma_bf16(d[1][2 * j],     aH1, bL);
                mma_bf16(d[0][2 * j + 1], aH0, bL + 2);
                mma_bf16(d[1][2 * j + 1], aH1, bL + 2);
                mma_bf16(d[0][2 * j],     aL0, bH);
                mma_bf16(d[1][2 * j],     aL1, bH);
                mma_bf16(d[0][2 * j + 1], aL0, bH + 2);
                mma_bf16(d[1][2 * j + 1], aL1, bH + 2);
            }
        }

        #pragma unroll
        for (int j = 0; j < 8; ++j)
            #pragma unroll
            for (int c = 0; c < 2; ++c) {
                float m = fmaxf(fmaxf(d[0][j][c], d[0][j][c + 2]),
                                fmaxf(d[1][j][c], d[1][j][c + 2]));
                runmax[j * 2 + c] = fmaxf(runmax[j * 2 + c], m);
            }
    }

    #pragma unroll
    for (int i = 0; i < 16; ++i) {
        float v = runmax[i];
        v = fmaxf(v, __shfl_xor_sync(0xffffffffu, v, 4));
        v = fmaxf(v, __shfl_xor_sync(0xffffffffu, v, 8));
        v = fmaxf(v, __shfl_xor_sync(0xffffffffu, v, 16));
        runmax[i] = v;
    }
    if (lane < 4) {
        #pragma unroll
        for (int j = 0; j < 8; ++j)
            #pragma unroll
            for (int c = 0; c < 2; ++c)
                scratch[wm * 256 + wn * 64 + j * 8 + lane * 2 + c] = runmax[j * 2 + c];
    }
    __syncthreads();
    if (tid < 256) {
        float m = fmaxf(fmaxf(scratch[tid], scratch[256 + tid]),
                        fmaxf(scratch[512 + tid], scratch[768 + tid]));
        g_G[b * 1024 + colBase + tid] = fmaxf(m + b3s[tid], 0.0f);
    }
}

// ---------------------------------------------------------------------------
// Head GEMMs: C = act(A @ B + bias). 32x64 block tile, 2x4 per thread,
// more CTAs to fix latency starvation (grid 64 / 32).
// ---------------------------------------------------------------------------
__device__ __forceinline__ void head_gemm_32(
    const float* __restrict__ A, const float* __restrict__ B,
    const float* __restrict__ bias, float* __restrict__ C,
    int K, int ldb, bool relu)
{
    float* As = (float*)smem_raw;    // 32 * 68
    float* Bs = As + 32 * 68;        // 64 * 64
    const int tid = threadIdx.x;
    const int tx = tid & 15, ty = tid >> 4;
    const int rowBase = blockIdx.x * 32;
    const int colBase = blockIdx.y * 64;

    float acc[2][4];
    #pragma unroll
    for (int p = 0; p < 2; ++p)
        #pragma unroll
        for (int c = 0; c < 4; ++c) acc[p][c] = 0.0f;

    for (int k0 = 0; k0 < K; k0 += 64) {
        __syncthreads();
        for (int i = tid * 4; i < 2048; i += 1024) {
            int r = i >> 6, k = i & 63;
            *(float4*)(As + r * 68 + k) = *(const float4*)(A + (size_t)(rowBase + r) * K + k0 + k);
        }
        for (int i = tid * 4; i < 4096; i += 1024) {
            int k = i >> 6, c = i & 63;
            *(float4*)(Bs + k * 64 + c) = *(const float4*)(B + (size_t)(k0 + k) * ldb + colBase + c);
        }
        __syncthreads();

        #pragma unroll 16
        for (int k = 0; k < 64; ++k) {
            const float4 w = *(const float4*)(Bs + k * 64 + tx * 4);
            const float a0 = As[(ty * 2 + 0) * 68 + k];
            const float a1 = As[(ty * 2 + 1) * 68 + k];
            acc[0][0] = fmaf(a0, w.x, acc[0][0]); acc[0][1] = fmaf(a0, w.y, acc[0][1]);
            acc[0][2] = fmaf(a0, w.z, acc[0][2]); acc[0][3] = fmaf(a0, w.w, acc[0][3]);
            acc[1][0] = fmaf(a1, w.x, acc[1][0]); acc[1][1] = fmaf(a1, w.y, acc[1][1]);
            acc[1][2] = fmaf(a1, w.z, acc[1][2]); acc[1][3] = fmaf(a1, w.w, acc[1][3]);
        }
    }

    #pragma unroll
    for (int p = 0; p < 2; ++p) {
        #pragma unroll
        for (int c = 0; c < 4; ++c) {
            float v = acc[p][c] + bias[colBase + tx * 4 + c];
            if (relu) v = fmaxf(v, 0.0f);
            C[(size_t)(rowBase + ty * 2 + p) * ldb + colBase + tx * 4 + c] = v;
        }
    }
}

__global__ void k3_head1(const float* __restrict__ Wh1, const float* __restrict__ bh1) {
    head_gemm_32(g_G, Wh1, bh1, g_Z1, 1024, 512, true);
}
__global__ void k4_head2(const float* __restrict__ Wh2, const float* __restrict__ bh2) {
    head_gemm_32(g_Z1, Wh2, bh2, g_Z2, 512, 256, true);
}

// ---------------------------------------------------------------------------
// K5: raw = Z2 @ Wh3 + bh3
// ---------------------------------------------------------------------------
__global__ void k5_raw(const float* __restrict__ Wh3, const float* __restrict__ bh3)
{
    int i = blockIdx.x * 256 + threadIdx.x;
    if (i >= BATCH * 9) return;
    int b = i / 9, j = i % 9;
    float acc = bh3[j];
    const float* z = g_Z2 + b * 256;
    #pragma unroll 8
    for (int k = 0; k < 256; ++k) acc = fmaf(z[k], Wh3[k * 9 + j], acc);
    g_RAW[i] = acc;
}

// ---------------------------------------------------------------------------
// K6: SVD projection onto SO(3). One thread per 3x3 matrix.
// ---------------------------------------------------------------------------
__device__ __forceinline__ void jrot(float A[3][3], float V[3][3], int p, int q)
{
    float apq = A[p][q];
    if (fabsf(apq) < 1e-20f) return;
    float tau = (A[q][q] - A[p][p]) / (2.0f * apq);
    float t = copysignf(1.0f, tau) / (fabsf(tau) + sqrtf(1.0f + tau * tau));
    float c = 1.0f / sqrtf(1.0f + t * t);
    float s = t * c;
    for (int r = 0; r < 3; ++r) {
        float arp = A[r][p], arq = A[r][q];
        A[r][p] = c * arp - s * arq;
        A[r][q] = s * arp + c * arq;
    }
    for (int r = 0; r < 3; ++r) {
        float apr = A[p][r], aqr = A[q][r];
        A[p][r] = c * apr - s * aqr;
        A[q][r] = s * apr + c * aqr;
    }
    for (int r = 0; r < 3; ++r) {
        float vrp = V[r][p], vrq = V[r][q];
        V[r][p] = c * vrp - s * vrq;
        V[r][q] = s * vrp + c * vrq;
    }
}

__global__ void k6_svd(float* __restrict__ out)
{
    int i = blockIdx.x * 32 + threadIdx.x;
    if (i >= BATCH) return;

    float M[3][3];
    for (int r = 0; r < 3; ++r)
        for (int c = 0; c < 3; ++c)
            M[r][c] = g_RAW[i * 9 + r * 3 + c];

    float A[3][3], V[3][3];
    for (int r = 0; r < 3; ++r)
        for (int c = 0; c < 3; ++c) {
            A[r][c] = M[0][r] * M[0][c] + M[1][r] * M[1][c] + M[2][r] * M[2][c];
            V[r][c] = (r == c) ? 1.0f : 0.0f;
        }

    for (int sweep = 0; sweep < 12; ++sweep) {
        jrot(A, V, 0, 1);
        jrot(A, V, 0, 2);
        jrot(A, V, 1, 2);
    }

    float e0 = A[0][0], e1 = A[1][1], e2 = A[2][2];
    int i0 = 0, i1 = 1, i2 = 2;
    if (e0 < e1) { float t = e0; e0 = e1; e1 = t; int ti = i0; i0 = i1; i1 = ti; }
    if (e0 < e2) { float t = e0; e0 = e2; e2 = t; int ti = i0; i0 = i2; i2 = ti; }
    if (e1 < e2) { float t = e1; e1 = e2; e2 = t; int ti = i1; i1 = i2; i2 = ti; }

    float v1[3], v2[3], v3[3];
    for (int r = 0; r < 3; ++r) { v1[r] = V[r][i0]; v2[r] = V[r][i1]; v3[r] = V[r][i2]; }

    float detV = v1[0] * (v2[1] * v3[2] - v2[2] * v3[1])
               - v1[1] * (v2[0] * v3[2] - v2[2] * v3[0])
               + v1[2] * (v2[0] * v3[1] - v2[1] * v3[0]);

    float w1[3], w2[3];
    for (int r = 0; r < 3; ++r) {
        w1[r] = M[r][0] * v1[0] + M[r][1] * v1[1] + M[r][2] * v1[2];
        w2[r] = M[r][0] * v2[0] + M[r][1] * v2[1] + M[r][2] * v2[2];
    }
    float n1 = sqrtf(w1[0] * w1[0] + w1[1] * w1[1] + w1[2] * w1[2] + 1e-30f);
    float u1[3] = { w1[0] / n1, w1[1] / n1, w1[2] / n1 };
    float d12 = u1[0] * w2[0] + u1[1] * w2[1] + u1[2] * w2[2];
    for (int r = 0; r < 3; ++r) w2[r] -= d12 * u1[r];
    float n2 = sqrtf(w2[0] * w2[0] + w2[1] * w2[1] + w2[2] * w2[2] + 1e-30f);
    float u2[3] = { w2[0] / n2, w2[1] / n2, w2[2] / n2 };
    float u3[3] = { u1[1] * u2[2] - u1[2] * u2[1],
                    u1[2] * u2[0] - u1[0] * u2[2],
                    u1[0] * u2[1] - u1[1] * u2[0] };
    if (detV < 0.0f) { u3[0] = -u3[0]; u3[1] = -u3[1]; u3[2] = -u3[2]; }

    for (int r = 0; r < 3; ++r)
        for (int c = 0; c < 3; ++c)
            out[i * 9 + r * 3 + c] = u1[r] * v1[c] + u2[r] * v2[c] + u3[r] * v3[c];
}

// ---------------------------------------------------------------------------
extern "C" void kernel_launch(void* const* d_in, const int* in_sizes, int n_in,
                              void* d_out, int out_size)
{
    const float* x   = (const float*)d_in[0];
    const float* W1  = (const float*)d_in[1];
    const float* b1  = (const float*)d_in[2];
    const float* W2  = (const float*)d_in[3];
    const float* b2  = (const float*)d_in[4];
    const float* W3  = (const float*)d_in[5];
    const float* b3  = (const float*)d_in[6];
    const float* Wh1 = (const float*)d_in[7];
    const float* bh1 = (const float*)d_in[8];
    const float* Wh2 = (const float*)d_in[9];
    const float* bh2 = (const float*)d_in[10];
    const float* Wh3 = (const float*)d_in[11];
    const float* bh3 = (const float*)d_in[12];
    float* out = (float*)d_out;

    const int smem3 = (32 * 68 + 64 * 64) * 4;   // 25088 B

    cudaFuncSetAttribute(k1_point_mlp,    cudaFuncAttributeMaxDynamicSharedMemorySize, K1_SMEM);
    cudaFuncSetAttribute(k2_gemm_max_mma, cudaFuncAttributeMaxDynamicSharedMemorySize, K2_SMEM);

    k1_point_mlp<<<2048, 512, K1_SMEM>>>(x, W1, b1, W2, b2);
    k2_gemm_max_mma<<<dim3(256, 4), 512, K2_SMEM>>>(W3, b3);
    k3_head1<<<dim3(8, 8), 256, smem3>>>(Wh1, bh1);
    k4_head2<<<dim3(8, 4), 256, smem3>>>(Wh2, bh2);
    k5_raw<<<9, 256>>>(Wh3, bh3);
    k6_svd<<<8, 32>>>(out);

    (void)in_sizes; (void)n_in; (void)out_size;
}

// round 6
// speedup vs baseline: 2.7477x; 1.1543x over previous
#include <cuda_runtime.h>
#include <cuda_bf16.h>
#include <math.h>
#include <cstdint>

#define BATCH 256
#define NPTS  1024

// Scratch (device globals — allocation-free contract)
__device__ __nv_bfloat16 g_H2hi[BATCH * NPTS * 128];   // 64 MB
__device__ __nv_bfloat16 g_H2lo[BATCH * NPTS * 128];   // 64 MB
__device__ float g_G[BATCH * 1024];
__device__ float g_Z1[BATCH * 512];
__device__ float g_Z2[BATCH * 256];
__device__ float g_RAW[BATCH * 9];

extern __shared__ char smem_raw[];

__device__ __forceinline__ uint32_t smem_u32(const void* p) {
    uint32_t a;
    asm("{ .reg .u64 t; cvta.to.shared.u64 t, %1; cvt.u32.u64 %0, t; }" : "=r"(a) : "l"(p));
    return a;
}

#define LDSM_X4(r0, r1, r2, r3, addr) \
    asm volatile("ldmatrix.sync.aligned.m8n8.x4.shared.b16 {%0,%1,%2,%3}, [%4];" \
                 : "=r"(r0), "=r"(r1), "=r"(r2), "=r"(r3) : "r"(addr))

__device__ __forceinline__ void mma_bf16(float* d, const uint32_t* a, const uint32_t* b) {
    asm volatile("mma.sync.aligned.m16n8k16.row.col.f32.bf16.bf16.f32 "
                 "{%0,%1,%2,%3},{%4,%5,%6,%7},{%8,%9},{%0,%1,%2,%3};"
                 : "+f"(d[0]), "+f"(d[1]), "+f"(d[2]), "+f"(d[3])
                 : "r"(a[0]), "r"(a[1]), "r"(a[2]), "r"(a[3]), "r"(b[0]), "r"(b[1]));
}

__device__ __forceinline__ uint32_t bf2u(__nv_bfloat162 v) {
    uint32_t u; *(__nv_bfloat162*)&u = v; return u;
}

#define CP_ASYNC16(dst, src) \
    asm volatile("cp.async.cg.shared.global [%0], [%1], 16;" :: "r"(dst), "l"(src))
#define CP_COMMIT() asm volatile("cp.async.commit_group;" ::: "memory")
#define CP_WAIT(n)  asm volatile("cp.async.wait_group %0;" :: "n"(n) : "memory")

// ---------------------------------------------------------------------------
// K1: per-point MLP 3 -> 64 (scalar) -> 128 (HMMA, 3-combo hi/lo bf16),
// fused bias+ReLU+split epilogue, writes g_H2hi/g_H2lo.
// ---------------------------------------------------------------------------
#define K1_LDP 144
#define K1_A_HI 0
#define K1_A_LO 18432
#define K1_B_HI 36864
#define K1_B_LO 55296
#define K1_W1S  73728
#define K1_B1S  74496
#define K1_B2S  74752
#define K1_SMEM 75264

__global__ void __launch_bounds__(512, 1) k1_point_mlp(
    const float* __restrict__ x,
    const float* __restrict__ W1, const float* __restrict__ b1,
    const float* __restrict__ W2, const float* __restrict__ b2)
{
    char* sm = smem_raw;
    const uint32_t sb = smem_u32(sm);
    const int tid = threadIdx.x, lane = tid & 31, w = tid >> 5;
    const int wm = w & 3, wn = w >> 2;
    float* W1s = (float*)(sm + K1_W1S);
    float* b1s = (float*)(sm + K1_B1S);
    float* b2s = (float*)(sm + K1_B2S);

    for (int i = tid; i < 8192; i += 512) {
        const int n = i & 127, k = i >> 7;
        const float v = W2[k * 128 + n];
        const __nv_bfloat16 h = __float2bfloat16(v);
        const __nv_bfloat16 l = __float2bfloat16(v - __bfloat162float(h));
        *(__nv_bfloat16*)(sm + K1_B_HI + n * K1_LDP + k * 2) = h;
        *(__nv_bfloat16*)(sm + K1_B_LO + n * K1_LDP + k * 2) = l;
    }
    if (tid < 192) W1s[tid] = W1[tid];
    else if (tid >= 256 && tid < 320) b1s[tid - 256] = b1[tid - 256];
    else if (tid >= 384 && tid < 512) b2s[tid - 384] = b2[tid - 384];
    __syncthreads();

    {
        const int pl = tid & 127;
        const int ks = (tid >> 7) * 16;
        const int pg = blockIdx.x * 128 + pl;
        const float x0 = x[pg * 3 + 0];
        const float x1 = x[pg * 3 + 1];
        const float x2 = x[pg * 3 + 2];
        #pragma unroll
        for (int kk = 0; kk < 16; kk += 2) {
            const int k = ks + kk;
            float va = fmaxf(fmaf(x0, W1s[k],     fmaf(x1, W1s[64 + k],     fmaf(x2, W1s[128 + k],     b1s[k]))), 0.0f);
            float vb = fmaxf(fmaf(x0, W1s[k + 1], fmaf(x1, W1s[64 + k + 1], fmaf(x2, W1s[128 + k + 1], b1s[k + 1]))), 0.0f);
            __nv_bfloat162 h = __floats2bfloat162_rn(va, vb);
            __nv_bfloat162 l = __floats2bfloat162_rn(va - __bfloat162float(h.x), vb - __bfloat162float(h.y));
            *(uint32_t*)(sm + K1_A_HI + pl * K1_LDP + k * 2) = bf2u(h);
            *(uint32_t*)(sm + K1_A_LO + pl * K1_LDP + k * 2) = bf2u(l);
        }
    }
    __syncthreads();

    const uint32_t aRow = (uint32_t)(wm * 32 + (lane & 15));
    const uint32_t aCol = (uint32_t)((lane >> 4) * 16);
    const uint32_t aHi0 = sb + K1_A_HI + aRow * K1_LDP + aCol;
    const uint32_t aHi1 = aHi0 + 16 * K1_LDP;
    const uint32_t aLo0 = sb + K1_A_LO + aRow * K1_LDP + aCol;
    const uint32_t aLo1 = aLo0 + 16 * K1_LDP;
    const uint32_t bRow = (uint32_t)(wn * 32 + (lane & 7) + ((lane >> 4) << 3));
    const uint32_t bCol = (uint32_t)(((lane >> 3) & 1) * 16);
    const uint32_t bHi0 = sb + K1_B_HI + bRow * K1_LDP + bCol;
    const uint32_t bLo0 = sb + K1_B_LO + bRow * K1_LDP + bCol;

    float d[2][4][4];
    #pragma unroll
    for (int mt = 0; mt < 2; ++mt)
        #pragma unroll
        for (int j = 0; j < 4; ++j)
            #pragma unroll
            for (int c = 0; c < 4; ++c) d[mt][j][c] = 0.0f;

    #pragma unroll
    for (int ks = 0; ks < 4; ++ks) {
        const uint32_t ko = ks * 32;
        uint32_t aH0[4], aH1[4], aL0[4], aL1[4];
        LDSM_X4(aH0[0], aH0[1], aH0[2], aH0[3], aHi0 + ko);
        LDSM_X4(aH1[0], aH1[1], aH1[2], aH1[3], aHi1 + ko);
        LDSM_X4(aL0[0], aL0[1], aL0[2], aL0[3], aLo0 + ko);
        LDSM_X4(aL1[0], aL1[1], aL1[2], aL1[3], aLo1 + ko);
        #pragma unroll
        for (int j = 0; j < 2; ++j) {
            uint32_t bH[4], bL[4];
            LDSM_X4(bH[0], bH[1], bH[2], bH[3], bHi0 + j * (16 * K1_LDP) + ko);
            LDSM_X4(bL[0], bL[1], bL[2], bL[3], bLo0 + j * (16 * K1_LDP) + ko);
            mma_bf16(d[0][2 * j],     aH0, bH);
            mma_bf16(d[1][2 * j],     aH1, bH);
            mma_bf16(d[0][2 * j + 1], aH0, bH + 2);
            mma_bf16(d[1][2 * j + 1], aH1, bH + 2);
            mma_bf16(d[0][2 * j],     aH0, bL);
            mma_bf16(d[1][2 * j],     aH1, bL);
            mma_bf16(d[0][2 * j + 1], aH0, bL + 2);
            mma_bf16(d[1][2 * j + 1], aH1, bL + 2);
            mma_bf16(d[0][2 * j],     aL0, bH);
            mma_bf16(d[1][2 * j],     aL1, bH);
            mma_bf16(d[0][2 * j + 1], aL0, bH + 2);
            mma_bf16(d[1][2 * j + 1], aL1, bH + 2);
        }
    }

    const int pBase = blockIdx.x * 128;
    #pragma unroll
    for (int mt = 0; mt < 2; ++mt) {
        #pragma unroll
        for (int j = 0; j < 4; ++j) {
            const int col = wn * 32 + j * 8 + (lane & 3) * 2;
            const float bc0 = b2s[col], bc1 = b2s[col + 1];
            #pragma unroll
            for (int rr = 0; rr < 2; ++rr) {
                const int row = pBase + wm * 32 + mt * 16 + (lane >> 2) + rr * 8;
                const float v0 = fmaxf(d[mt][j][rr * 2 + 0] + bc0, 0.0f);
                const float v1 = fmaxf(d[mt][j][rr * 2 + 1] + bc1, 0.0f);
                __nv_bfloat162 h = __floats2bfloat162_rn(v0, v1);
                __nv_bfloat162 l = __floats2bfloat162_rn(v0 - __bfloat162float(h.x), v1 - __bfloat162float(h.y));
                *(uint32_t*)(g_H2hi + (size_t)row * 128 + col) = bf2u(h);
                *(uint32_t*)(g_H2lo + (size_t)row * 128 + col) = bf2u(l);
            }
        }
    }
}

// ---------------------------------------------------------------------------
// K2: HMMA fused GEMM + max-pool, cp.async double-buffered 64-row A tiles.
// CTA = (batch, 256-col group), 512 threads = 16 warps (2 m x 8 n), warp 32x32.
// ---------------------------------------------------------------------------
#define LDP 272
#define A_STAGE 17408                 // 64*272
#define OFF_A 0                       // 4 buffers: s0hi, s0lo, s1hi, s1lo
#define OFF_B_HI 69632
#define OFF_B_LO 139264
#define OFF_SCR  208896               // float[2][256]
#define OFF_B3   210944               // float[256]
#define K2_SMEM  211968

__global__ void __launch_bounds__(512, 1) k2_gemm_max_mma(const float* __restrict__ W3,
                                                          const float* __restrict__ b3)
{
    char* sm = smem_raw;
    const uint32_t sb = smem_u32(sm);
    const int tid = threadIdx.x, lane = tid & 31, w = tid >> 5;
    const int wm = w & 1, wn = w >> 1;
    const int b = blockIdx.x;
    const int colBase = blockIdx.y * 256;

    float* scratch = (float*)(sm + OFF_SCR);
    float* b3s     = (float*)(sm + OFF_B3);

    const __nv_bfloat16* srcHi = g_H2hi + (size_t)b * NPTS * 128;
    const __nv_bfloat16* srcLo = g_H2lo + (size_t)b * NPTS * 128;

    const int am0 = tid >> 4, aj0 = (tid & 15);            // rows 0..31
    const int am1 = 32 + (tid >> 4), aj1 = (tid & 15);     // rows 32..63

    // Issue tile 0 loads first so they overlap the B conversion fill.
    {
        const uint32_t dstHi = sb + OFF_A;
        const uint32_t dstLo = sb + OFF_A + A_STAGE;
        CP_ASYNC16(dstHi + am0 * LDP + aj0 * 16, (const char*)srcHi + (am0 * 16 + aj0) * 16);
        CP_ASYNC16(dstHi + am1 * LDP + aj1 * 16, (const char*)srcHi + (am1 * 16 + aj1) * 16);
        CP_ASYNC16(dstLo + am0 * LDP + aj0 * 16, (const char*)srcLo + (am0 * 16 + aj0) * 16);
        CP_ASYNC16(dstLo + am1 * LDP + aj1 * 16, (const char*)srcLo + (am1 * 16 + aj1) * 16);
        CP_COMMIT();
    }

    // B fill: Bs[n][k] = W3[k][colBase+n] split hi/lo (once per CTA)
    for (int idx = tid; idx < 32768; idx += 512) {
        const int n = idx & 255, k = idx >> 8;
        const float v = W3[k * 1024 + colBase + n];
        const __nv_bfloat16 h = __float2bfloat16(v);
        const __nv_bfloat16 l = __float2bfloat16(v - __bfloat162float(h));
        *(__nv_bfloat16*)(sm + OFF_B_HI + n * LDP + k * 2) = h;
        *(__nv_bfloat16*)(sm + OFF_B_LO + n * LDP + k * 2) = l;
    }
    if (tid < 256) b3s[tid] = b3[colBase + tid];

    const uint32_t aRow = (uint32_t)(wm * 32 + (lane & 15));
    const uint32_t aCol = (uint32_t)((lane >> 4) * 16);
    const uint32_t aOffHi = aRow * LDP + aCol;
    const uint32_t bRow = (uint32_t)(wn * 32 + (lane & 7) + ((lane >> 4) << 3));
    const uint32_t bCol = (uint32_t)(((lane >> 3) & 1) * 16);
    const uint32_t bHi0 = sb + OFF_B_HI + bRow * LDP + bCol;
    const uint32_t bLo0 = sb + OFF_B_LO + bRow * LDP + bCol;

    float runmax[8];
    #pragma unroll
    for (int i = 0; i < 8; ++i) runmax[i] = -1e30f;

    for (int t = 0; t < 16; ++t) {
        if (t < 15) {
            const uint32_t dstHi = sb + OFF_A + ((t + 1) & 1) * (2 * A_STAGE);
            const uint32_t dstLo = dstHi + A_STAGE;
            const int base = (t + 1) * 64 * 16;
            CP_ASYNC16(dstHi + am0 * LDP + aj0 * 16, (const char*)srcHi + (base + am0 * 16 + aj0) * 16);
            CP_ASYNC16(dstHi + am1 * LDP + aj1 * 16, (const char*)srcHi + (base + am1 * 16 + aj1) * 16);
            CP_ASYNC16(dstLo + am0 * LDP + aj0 * 16, (const char*)srcLo + (base + am0 * 16 + aj0) * 16);
            CP_ASYNC16(dstLo + am1 * LDP + aj1 * 16, (const char*)srcLo + (base + am1 * 16 + aj1) * 16);
            CP_COMMIT();
            CP_WAIT(1);
        } else {
            CP_WAIT(0);
        }
        __syncthreads();

        const uint32_t stage = sb + OFF_A + (t & 1) * (2 * A_STAGE);
        const uint32_t aHi0 = stage + aOffHi;
        const uint32_t aLo0 = stage + A_STAGE + aOffHi;

        float d[2][4][4];
        #pragma unroll
        for (int mt = 0; mt < 2; ++mt)
            #pragma unroll
            for (int j = 0; j < 4; ++j)
                #pragma unroll
                for (int c = 0; c < 4; ++c) d[mt][j][c] = 0.0f;

        #pragma unroll
        for (int ks = 0; ks < 8; ++ks) {
            const uint32_t ko = ks * 32;
            uint32_t aH0[4], aH1[4], aL0[4], aL1[4];
            LDSM_X4(aH0[0], aH0[1], aH0[2], aH0[3], aHi0 + ko);
            LDSM_X4(aH1[0], aH1[1], aH1[2], aH1[3], aHi0 + 16 * LDP + ko);
            LDSM_X4(aL0[0], aL0[1], aL0[2], aL0[3], aLo0 + ko);
            LDSM_X4(aL1[0], aL1[1], aL1[2], aL1[3], aLo0 + 16 * LDP + ko);
            #pragma unroll
            for (int j = 0; j < 2; ++j) {
                uint32_t bH[4], bL[4];
                LDSM_X4(bH[0], bH[1], bH[2], bH[3], bHi0 + j * (16 * LDP) + ko);
                LDSM_X4(bL[0], bL[1], bL[2], bL[3], bLo0 + j * (16 * LDP) + ko);
                mma_bf16(d[0][2 * j],     aH0, bH);
                mma_bf16(d[1][2 * j],     aH1, bH);
                mma_bf16(d[0][2 * j + 1], aH0, bH + 2);
                mma_bf16(d[1][2 * j + 1], aH1, bH + 2);
                mma_bf16(d[0][2 * j],     aH0, bL);
                mma_bf16(d[1][2 * j],     aH1, bL);
                mma_bf16(d[0][2 * j + 1], aH0, bL + 2);
                mma_bf16(d[1][2 * j + 1], aH1, bL + 2);
                mma_bf16(d[0][2 * j],     aL0, bH);
                mma_bf16(d[1][2 * j],     aL1, bH);
                mma_bf16(d[0][2 * j + 1], aL0, bH + 2);
                mma_bf16(d[1][2 * j + 1], aL1, bH + 2);
            }
        }

        #pragma unroll
        for (int j = 0; j < 4; ++j)
            #pragma unroll
            for (int c = 0; c < 2; ++c) {
                float m = fmaxf(fmaxf(d[0][j][c], d[0][j][c + 2]),
                                fmaxf(d[1][j][c], d[1][j][c + 2]));
                runmax[j * 2 + c] = fmaxf(runmax[j * 2 + c], m);
            }
        __syncthreads();
    }

    #pragma unroll
    for (int i = 0; i < 8; ++i) {
        float v = runmax[i];
        v = fmaxf(v, __shfl_xor_sync(0xffffffffu, v, 4));
        v = fmaxf(v, __shfl_xor_sync(0xffffffffu, v, 8));
        v = fmaxf(v, __shfl_xor_sync(0xffffffffu, v, 16));
        runmax[i] = v;
    }
    if (lane < 4) {
        #pragma unroll
        for (int j = 0; j < 4; ++j)
            #pragma unroll
            for (int c = 0; c < 2; ++c)
                scratch[wm * 256 + wn * 32 + j * 8 + lane * 2 + c] = runmax[j * 2 + c];
    }
    __syncthreads();
    if (tid < 256) {
        float m = fmaxf(scratch[tid], scratch[256 + tid]);
        g_G[b * 1024 + colBase + tid] = fmaxf(m + b3s[tid], 0.0f);
    }
}

// ---------------------------------------------------------------------------
// Head GEMMs: C = act(A @ B + bias). 32x64 tile, cp.async double-buffered.
// 256 threads: A tile = 512 f4 slots (2/thread), B tile = 1024 f4 slots (4/thread).
// ---------------------------------------------------------------------------
#define HD_AS 2176    // 32*68 floats
#define HD_BS 4096    // 64*64 floats
#define HD_STAGE (HD_AS + HD_BS)
#define HD_SMEM (2 * HD_STAGE * 4)

__device__ __forceinline__ void hd_load_chunk(
    uint32_t as, uint32_t bs,
    const float* __restrict__ A, const float* __restrict__ B,
    int rowBase, int colBase, int K, int ldb, int k0, int tid)
{
    #pragma unroll
    for (int i = 0; i < 2; ++i) {
        const int idx = tid + i * 256;
        const int r = idx >> 4, k = (idx & 15) * 4;
        CP_ASYNC16(as + (r * 68 + k) * 4, A + (size_t)(rowBase + r) * K + k0 + k);
    }
    #pragma unroll
    for (int i = 0; i < 4; ++i) {
        const int idx = tid + i * 256;
        const int r = idx >> 4, c = (idx & 15) * 4;
        CP_ASYNC16(bs + (r * 64 + c) * 4, B + (size_t)(k0 + r) * ldb + colBase + c);
    }
}

__device__ __forceinline__ void head_gemm_32(
    const float* __restrict__ A, const float* __restrict__ B,
    const float* __restrict__ bias, float* __restrict__ C,
    int K, int ldb, bool relu)
{
    float* sm = (float*)smem_raw;
    const uint32_t sb = smem_u32(sm);
    const int tid = threadIdx.x;
    const int tx = tid & 15, ty = tid >> 4;
    const int rowBase = blockIdx.x * 32;
    const int colBase = blockIdx.y * 64;
    const int nChunks = K >> 6;

    hd_load_chunk(sb, sb + HD_AS * 4, A, B, rowBase, colBase, K, ldb, 0, tid);
    CP_COMMIT();

    float acc[2][4];
    #pragma unroll
    for (int p = 0; p < 2; ++p)
        #pragma unroll
        for (int c = 0; c < 4; ++c) acc[p][c] = 0.0f;

    for (int ch = 0; ch < nChunks; ++ch) {
        if (ch + 1 < nChunks) {
            const uint32_t as = sb + ((ch + 1) & 1) * HD_STAGE * 4;
            hd_load_chunk(as, as + HD_AS * 4, A, B, rowBase, colBase, K, ldb, (ch + 1) * 64, tid);
            CP_COMMIT();
            CP_WAIT(1);
        } else {
            CP_WAIT(0);
        }
        __syncthreads();

        const float* As = sm + (ch & 1) * HD_STAGE;
        const float* Bs = As + HD_AS;

        #pragma unroll 16
        for (int k = 0; k < 64; ++k) {
            const float4 wv = *(const float4*)(Bs + k * 64 + tx * 4);
            const float a0 = As[(ty * 2 + 0) * 68 + k];
            const float a1 = As[(ty * 2 + 1) * 68 + k];
            acc[0][0] = fmaf(a0, wv.x, acc[0][0]); acc[0][1] = fmaf(a0, wv.y, acc[0][1]);
            acc[0][2] = fmaf(a0, wv.z, acc[0][2]); acc[0][3] = fmaf(a0, wv.w, acc[0][3]);
            acc[1][0] = fmaf(a1, wv.x, acc[1][0]); acc[1][1] = fmaf(a1, wv.y, acc[1][1]);
            acc[1][2] = fmaf(a1, wv.z, acc[1][2]); acc[1][3] = fmaf(a1, wv.w, acc[1][3]);
        }
        __syncthreads();
    }

    #pragma unroll
    for (int p = 0; p < 2; ++p) {
        #pragma unroll
        for (int c = 0; c < 4; ++c) {
            float v = acc[p][c] + bias[colBase + tx * 4 + c];
            if (relu) v = fmaxf(v, 0.0f);
            C[(size_t)(rowBase + ty * 2 + p) * ldb + colBase + tx * 4 + c] = v;
        }
    }
}

__global__ void k3_head1(const float* __restrict__ Wh1, const float* __restrict__ bh1) {
    head_gemm_32(g_G, Wh1, bh1, g_Z1, 1024, 512, true);
}
__global__ void k4_head2(const float* __restrict__ Wh2, const float* __restrict__ bh2) {
    head_gemm_32(g_Z1, Wh2, bh2, g_Z2, 512, 256, true);
}

// ---------------------------------------------------------------------------
// K5: raw = Z2 @ Wh3 + bh3 — warp per output, shfl reduce.
// ---------------------------------------------------------------------------
__global__ void k5_raw(const float* __restrict__ Wh3, const float* __restrict__ bh3)
{
    const int g = blockIdx.x * 8 + (threadIdx.x >> 5);
    if (g >= BATCH * 9) return;
    const int lane = threadIdx.x & 31;
    const int b = g / 9, j = g % 9;
    const float* z = g_Z2 + b * 256;
    float acc = 0.0f;
    #pragma unroll
    for (int i = 0; i < 8; ++i) {
        const int k = lane + i * 32;
        acc = fmaf(z[k], Wh3[k * 9 + j], acc);
    }
    #pragma unroll
    for (int off = 16; off > 0; off >>= 1)
        acc += __shfl_xor_sync(0xffffffffu, acc, off);
    if (lane == 0) g_RAW[g] = acc + bh3[j];
}

// ---------------------------------------------------------------------------
// K6: SVD projection onto SO(3). One thread per 3x3 matrix.
// ---------------------------------------------------------------------------
__device__ __forceinline__ void jrot(float A[3][3], float V[3][3], int p, int q)
{
    float apq = A[p][q];
    if (fabsf(apq) < 1e-20f) return;
    float tau = (A[q][q] - A[p][p]) / (2.0f * apq);
    float t = copysignf(1.0f, tau) / (fabsf(tau) + sqrtf(1.0f + tau * tau));
    float c = 1.0f / sqrtf(1.0f + t * t);
    float s = t * c;
    for (int r = 0; r < 3; ++r) {
        float arp = A[r][p], arq = A[r][q];
        A[r][p] = c * arp - s * arq;
        A[r][q] = s * arp + c * arq;
    }
    for (int r = 0; r < 3; ++r) {
        float apr = A[p][r], aqr = A[q][r];
        A[p][r] = c * apr - s * aqr;
        A[q][r] = s * apr + c * aqr;
    }
    for (int r = 0; r < 3; ++r) {
        float vrp = V[r][p], vrq = V[r][q];
        V[r][p] = c * vrp - s * vrq;
        V[r][q] = s * vrp + c * vrq;
    }
}

__global__ void k6_svd(float* __restrict__ out)
{
    int i = blockIdx.x * 32 + threadIdx.x;
    if (i >= BATCH) return;

    float M[3][3];
    for (int r = 0; r < 3; ++r)
        for (int c = 0; c < 3; ++c)
            M[r][c] = g_RAW[i * 9 + r * 3 + c];

    float A[3][3], V[3][3];
    for (int r = 0; r < 3; ++r)
        for (int c = 0; c < 3; ++c) {
            A[r][c] = M[0][r] * M[0][c] + M[1][r] * M[1][c] + M[2][r] * M[2][c];
            V[r][c] = (r == c) ? 1.0f : 0.0f;
        }

    for (int sweep = 0; sweep < 12; ++sweep) {
        jrot(A, V, 0, 1);
        jrot(A, V, 0, 2);
        jrot(A, V, 1, 2);
    }

    float e0 = A[0][0], e1 = A[1][1], e2 = A[2][2];
    int i0 = 0, i1 = 1, i2 = 2;
    if (e0 < e1) { float t = e0; e0 = e1; e1 = t; int ti = i0; i0 = i1; i1 = ti; }
    if (e0 < e2) { float t = e0; e0 = e2; e2 = t; int ti = i0; i0 = i2; i2 = ti; }
    if (e1 < e2) { float t = e1; e1 = e2; e2 = t; int ti = i1; i1 = i2; i2 = ti; }

    float v1[3], v2[3], v3[3];
    for (int r = 0; r < 3; ++r) { v1[r] = V[r][i0]; v2[r] = V[r][i1]; v3[r] = V[r][i2]; }

    float detV = v1[0] * (v2[1] * v3[2] - v2[2] * v3[1])
               - v1[1] * (v2[0] * v3[2] - v2[2] * v3[0])
               + v1[2] * (v2[0] * v3[1] - v2[1] * v3[0]);

    float w1[3], w2[3];
    for (int r = 0; r < 3; ++r) {
        w1[r] = M[r][0] * v1[0] + M[r][1] * v1[1] + M[r][2] * v1[2];
        w2[r] = M[r][0] * v2[0] + M[r][1] * v2[1] + M[r][2] * v2[2];
    }
    float n1 = sqrtf(w1[0] * w1[0] + w1[1] * w1[1] + w1[2] * w1[2] + 1e-30f);
    float u1[3] = { w1[0] / n1, w1[1] / n1, w1[2] / n1 };
    float d12 = u1[0] * w2[0] + u1[1] * w2[1] + u1[2] * w2[2];
    for (int r = 0; r < 3; ++r) w2[r] -= d12 * u1[r];
    float n2 = sqrtf(w2[0] * w2[0] + w2[1] * w2[1] + w2[2] * w2[2] + 1e-30f);
    float u2[3] = { w2[0] / n2, w2[1] / n2, w2[2] / n2 };
    float u3[3] = { u1[1] * u2[2] - u1[2] * u2[1],
                    u1[2] * u2[0] - u1[0] * u2[2],
                    u1[0] * u2[1] - u1[1] * u2[0] };
    if (detV < 0.0f) { u3[0] = -u3[0]; u3[1] = -u3[1]; u3[2] = -u3[2]; }

    for (int r = 0; r < 3; ++r)
        for (int c = 0; c < 3; ++c)
            out[i * 9 + r * 3 + c] = u1[r] * v1[c] + u2[r] * v2[c] + u3[r] * v3[c];
}

// ---------------------------------------------------------------------------
extern "C" void kernel_launch(void* const* d_in, const int* in_sizes, int n_in,
                              void* d_out, int out_size)
{
    const float* x   = (const float*)d_in[0];
    const float* W1  = (const float*)d_in[1];
    const float* b1  = (const float*)d_in[2];
    const float* W2  = (const float*)d_in[3];
    const float* b2  = (const float*)d_in[4];
    const float* W3  = (const float*)d_in[5];
    const float* b3  = (const float*)d_in[6];
    const float* Wh1 = (const float*)d_in[7];
    const float* bh1 = (const float*)d_in[8];
    const float* Wh2 = (const float*)d_in[9];
    const float* bh2 = (const float*)d_in[10];
    const float* Wh3 = (const float*)d_in[11];
    const float* bh3 = (const float*)d_in[12];
    float* out = (float*)d_out;

    cudaFuncSetAttribute(k1_point_mlp,    cudaFuncAttributeMaxDynamicSharedMemorySize, K1_SMEM);
    cudaFuncSetAttribute(k2_gemm_max_mma, cudaFuncAttributeMaxDynamicSharedMemorySize, K2_SMEM);
    cudaFuncSetAttribute(k3_head1,        cudaFuncAttributeMaxDynamicSharedMemorySize, HD_SMEM);
    cudaFuncSetAttribute(k4_head2,        cudaFuncAttributeMaxDynamicSharedMemorySize, HD_SMEM);

    k1_point_mlp<<<2048, 512, K1_SMEM>>>(x, W1, b1, W2, b2);
    k2_gemm_max_mma<<<dim3(256, 4), 512, K2_SMEM>>>(W3, b3);
    k3_head1<<<dim3(8, 8), 256, HD_SMEM>>>(Wh1, bh1);
    k4_head2<<<dim3(8, 4), 256, HD_SMEM>>>(Wh2, bh2);
    k5_raw<<<288, 256>>>(Wh3, bh3);
    k6_svd<<<8, 32>>>(out);

    (void)in_sizes; (void)n_in; (void)out_size;
}

// round 7
// speedup vs baseline: 2.7814x; 1.0123x over previous
#include <cuda_runtime.h>
#include <cuda_bf16.h>
#include <math.h>
#include <cstdint>

#define BATCH 256
#define NPTS  1024

// Scratch (device globals — allocation-free contract)
__device__ __nv_bfloat16 g_H2hi[BATCH * NPTS * 128];   // 64 MB
__device__ __nv_bfloat16 g_H2lo[BATCH * NPTS * 128];   // 64 MB
__device__ float g_G[BATCH * 1024];
__device__ float g_Z1[BATCH * 512];
__device__ float g_Z2[BATCH * 256];
__device__ float g_RAW[BATCH * 9];

extern __shared__ char smem_raw[];

__device__ __forceinline__ uint32_t smem_u32(const void* p) {
    uint32_t a;
    asm("{ .reg .u64 t; cvta.to.shared.u64 t, %1; cvt.u32.u64 %0, t; }" : "=r"(a) : "l"(p));
    return a;
}

#define LDSM_X4(r0, r1, r2, r3, addr) \
    asm volatile("ldmatrix.sync.aligned.m8n8.x4.shared.b16 {%0,%1,%2,%3}, [%4];" \
                 : "=r"(r0), "=r"(r1), "=r"(r2), "=r"(r3) : "r"(addr))

__device__ __forceinline__ void mma_bf16(float* d, const uint32_t* a, const uint32_t* b) {
    asm volatile("mma.sync.aligned.m16n8k16.row.col.f32.bf16.bf16.f32 "
                 "{%0,%1,%2,%3},{%4,%5,%6,%7},{%8,%9},{%0,%1,%2,%3};"
                 : "+f"(d[0]), "+f"(d[1]), "+f"(d[2]), "+f"(d[3])
                 : "r"(a[0]), "r"(a[1]), "r"(a[2]), "r"(a[3]), "r"(b[0]), "r"(b[1]));
}

__device__ __forceinline__ uint32_t bf2u(__nv_bfloat162 v) {
    uint32_t u; *(__nv_bfloat162*)&u = v; return u;
}

#define CP_ASYNC16(dst, src) \
    asm volatile("cp.async.cg.shared.global [%0], [%1], 16;" :: "r"(dst), "l"(src))
#define CP_COMMIT() asm volatile("cp.async.commit_group;" ::: "memory")
#define CP_WAIT(n)  asm volatile("cp.async.wait_group %0;" :: "n"(n) : "memory")

// ---------------------------------------------------------------------------
// K1: per-point MLP 3 -> 64 (scalar) -> 128 (HMMA, 3-combo hi/lo bf16),
// fused bias+ReLU+split epilogue, writes g_H2hi/g_H2lo. (unchanged R6)
// ---------------------------------------------------------------------------
#define K1_LDP 144
#define K1_A_HI 0
#define K1_A_LO 18432
#define K1_B_HI 36864
#define K1_B_LO 55296
#define K1_W1S  73728
#define K1_B1S  74496
#define K1_B2S  74752
#define K1_SMEM 75264

__global__ void __launch_bounds__(512, 1) k1_point_mlp(
    const float* __restrict__ x,
    const float* __restrict__ W1, const float* __restrict__ b1,
    const float* __restrict__ W2, const float* __restrict__ b2)
{
    char* sm = smem_raw;
    const uint32_t sb = smem_u32(sm);
    const int tid = threadIdx.x, lane = tid & 31, w = tid >> 5;
    const int wm = w & 3, wn = w >> 2;
    float* W1s = (float*)(sm + K1_W1S);
    float* b1s = (float*)(sm + K1_B1S);
    float* b2s = (float*)(sm + K1_B2S);

    for (int i = tid; i < 8192; i += 512) {
        const int n = i & 127, k = i >> 7;
        const float v = W2[k * 128 + n];
        const __nv_bfloat16 h = __float2bfloat16(v);
        const __nv_bfloat16 l = __float2bfloat16(v - __bfloat162float(h));
        *(__nv_bfloat16*)(sm + K1_B_HI + n * K1_LDP + k * 2) = h;
        *(__nv_bfloat16*)(sm + K1_B_LO + n * K1_LDP + k * 2) = l;
    }
    if (tid < 192) W1s[tid] = W1[tid];
    else if (tid >= 256 && tid < 320) b1s[tid - 256] = b1[tid - 256];
    else if (tid >= 384 && tid < 512) b2s[tid - 384] = b2[tid - 384];
    __syncthreads();

    {
        const int pl = tid & 127;
        const int ks = (tid >> 7) * 16;
        const int pg = blockIdx.x * 128 + pl;
        const float x0 = x[pg * 3 + 0];
        const float x1 = x[pg * 3 + 1];
        const float x2 = x[pg * 3 + 2];
        #pragma unroll
        for (int kk = 0; kk < 16; kk += 2) {
            const int k = ks + kk;
            float va = fmaxf(fmaf(x0, W1s[k],     fmaf(x1, W1s[64 + k],     fmaf(x2, W1s[128 + k],     b1s[k]))), 0.0f);
            float vb = fmaxf(fmaf(x0, W1s[k + 1], fmaf(x1, W1s[64 + k + 1], fmaf(x2, W1s[128 + k + 1], b1s[k + 1]))), 0.0f);
            __nv_bfloat162 h = __floats2bfloat162_rn(va, vb);
            __nv_bfloat162 l = __floats2bfloat162_rn(va - __bfloat162float(h.x), vb - __bfloat162float(h.y));
            *(uint32_t*)(sm + K1_A_HI + pl * K1_LDP + k * 2) = bf2u(h);
            *(uint32_t*)(sm + K1_A_LO + pl * K1_LDP + k * 2) = bf2u(l);
        }
    }
    __syncthreads();

    const uint32_t aRow = (uint32_t)(wm * 32 + (lane & 15));
    const uint32_t aCol = (uint32_t)((lane >> 4) * 16);
    const uint32_t aHi0 = sb + K1_A_HI + aRow * K1_LDP + aCol;
    const uint32_t aHi1 = aHi0 + 16 * K1_LDP;
    const uint32_t aLo0 = sb + K1_A_LO + aRow * K1_LDP + aCol;
    const uint32_t aLo1 = aLo0 + 16 * K1_LDP;
    const uint32_t bRow = (uint32_t)(wn * 32 + (lane & 7) + ((lane >> 4) << 3));
    const uint32_t bCol = (uint32_t)(((lane >> 3) & 1) * 16);
    const uint32_t bHi0 = sb + K1_B_HI + bRow * K1_LDP + bCol;
    const uint32_t bLo0 = sb + K1_B_LO + bRow * K1_LDP + bCol;

    float d[2][4][4];
    #pragma unroll
    for (int mt = 0; mt < 2; ++mt)
        #pragma unroll
        for (int j = 0; j < 4; ++j)
            #pragma unroll
            for (int c = 0; c < 4; ++c) d[mt][j][c] = 0.0f;

    #pragma unroll
    for (int ks = 0; ks < 4; ++ks) {
        const uint32_t ko = ks * 32;
        uint32_t aH0[4], aH1[4], aL0[4], aL1[4];
        LDSM_X4(aH0[0], aH0[1], aH0[2], aH0[3], aHi0 + ko);
        LDSM_X4(aH1[0], aH1[1], aH1[2], aH1[3], aHi1 + ko);
        LDSM_X4(aL0[0], aL0[1], aL0[2], aL0[3], aLo0 + ko);
        LDSM_X4(aL1[0], aL1[1], aL1[2], aL1[3], aLo1 + ko);
        #pragma unroll
        for (int j = 0; j < 2; ++j) {
            uint32_t bH[4], bL[4];
            LDSM_X4(bH[0], bH[1], bH[2], bH[3], bHi0 + j * (16 * K1_LDP) + ko);
            LDSM_X4(bL[0], bL[1], bL[2], bL[3], bLo0 + j * (16 * K1_LDP) + ko);
            mma_bf16(d[0][2 * j],     aH0, bH);
            mma_bf16(d[1][2 * j],     aH1, bH);
            mma_bf16(d[0][2 * j + 1], aH0, bH + 2);
            mma_bf16(d[1][2 * j + 1], aH1, bH + 2);
            mma_bf16(d[0][2 * j],     aH0, bL);
            mma_bf16(d[1][2 * j],     aH1, bL);
            mma_bf16(d[0][2 * j + 1], aH0, bL + 2);
            mma_bf16(d[1][2 * j + 1], aH1, bL + 2);
            mma_bf16(d[0][2 * j],     aL0, bH);
            mma_bf16(d[1][2 * j],     aL1, bH);
            mma_bf16(d[0][2 * j + 1], aL0, bH + 2);
            mma_bf16(d[1][2 * j + 1], aL1, bH + 2);
        }
    }

    const int pBase = blockIdx.x * 128;
    #pragma unroll
    for (int mt = 0; mt < 2; ++mt) {
        #pragma unroll
        for (int j = 0; j < 4; ++j) {
            const int col = wn * 32 + j * 8 + (lane & 3) * 2;
            const float bc0 = b2s[col], bc1 = b2s[col + 1];
            #pragma unroll
            for (int rr = 0; rr < 2; ++rr) {
                const int row = pBase + wm * 32 + mt * 16 + (lane >> 2) + rr * 8;
                const float v0 = fmaxf(d[mt][j][rr * 2 + 0] + bc0, 0.0f);
                const float v1 = fmaxf(d[mt][j][rr * 2 + 1] + bc1, 0.0f);
                __nv_bfloat162 h = __floats2bfloat162_rn(v0, v1);
                __nv_bfloat162 l = __floats2bfloat162_rn(v0 - __bfloat162float(h.x), v1 - __bfloat162float(h.y));
                *(uint32_t*)(g_H2hi + (size_t)row * 128 + col) = bf2u(h);
                *(uint32_t*)(g_H2lo + (size_t)row * 128 + col) = bf2u(l);
            }
        }
    }
}

// ---------------------------------------------------------------------------
// K2: HMMA fused GEMM + max-pool, cp.async double-buffered 64-row A tiles.
// 256 threads = 8 warps (2m x 4n), warp tile 32x64: 25% less LDSM per MMA.
// Grid (colgroup, batch) so same-batch CTAs are launch-adjacent (L2 reuse).
// ---------------------------------------------------------------------------
#define LDP 272
#define A_STAGE 17408                 // 64*272
#define OFF_A 0                       // 4 buffers: s0hi, s0lo, s1hi, s1lo
#define OFF_B_HI 69632
#define OFF_B_LO 139264
#define OFF_SCR  208896               // float[2][256]
#define OFF_B3   210944               // float[256]
#define K2_SMEM  211968

__global__ void __launch_bounds__(256, 1) k2_gemm_max_mma(const float* __restrict__ W3,
                                                          const float* __restrict__ b3)
{
    char* sm = smem_raw;
    const uint32_t sb = smem_u32(sm);
    const int tid = threadIdx.x, lane = tid & 31, w = tid >> 5;
    const int wm = w & 1, wn = w >> 1;          // 2m x 4n
    const int b = blockIdx.y;
    const int colBase = blockIdx.x * 256;

    float* scratch = (float*)(sm + OFF_SCR);
    float* b3s     = (float*)(sm + OFF_B3);

    const __nv_bfloat16* srcHi = g_H2hi + (size_t)b * NPTS * 128;
    const __nv_bfloat16* srcLo = g_H2lo + (size_t)b * NPTS * 128;

    // Issue tile 0 loads first so they overlap the B conversion fill.
    // 1024 uint4 slots per buffer, 256 threads -> 4 each (x2 for hi+lo).
    {
        const uint32_t dstHi = sb + OFF_A;
        const uint32_t dstLo = sb + OFF_A + A_STAGE;
        #pragma unroll
        for (int i = 0; i < 4; ++i) {
            const int idx = tid + i * 256;
            const int m = idx >> 4, j = idx & 15;
            CP_ASYNC16(dstHi + m * LDP + j * 16, (const char*)srcHi + idx * 16);
            CP_ASYNC16(dstLo + m * LDP + j * 16, (const char*)srcLo + idx * 16);
        }
        CP_COMMIT();
    }

    // B fill: Bs[n][k] = W3[k][colBase+n] split hi/lo (once per CTA)
    for (int idx = tid; idx < 32768; idx += 256) {
        const int n = idx & 255, k = idx >> 8;
        const float v = W3[k * 1024 + colBase + n];
        const __nv_bfloat16 h = __float2bfloat16(v);
        const __nv_bfloat16 l = __float2bfloat16(v - __bfloat162float(h));
        *(__nv_bfloat16*)(sm + OFF_B_HI + n * LDP + k * 2) = h;
        *(__nv_bfloat16*)(sm + OFF_B_LO + n * LDP + k * 2) = l;
    }
    b3s[tid] = b3[colBase + tid];

    const uint32_t aRow = (uint32_t)(wm * 32 + (lane & 15));
    const uint32_t aCol = (uint32_t)((lane >> 4) * 16);
    const uint32_t aOffHi = aRow * LDP + aCol;
    const uint32_t bRow = (uint32_t)(wn * 64 + (lane & 7) + ((lane >> 4) << 3));
    const uint32_t bCol = (uint32_t)(((lane >> 3) & 1) * 16);
    const uint32_t bHi0 = sb + OFF_B_HI + bRow * LDP + bCol;
    const uint32_t bLo0 = sb + OFF_B_LO + bRow * LDP + bCol;

    float runmax[16];
    #pragma unroll
    for (int i = 0; i < 16; ++i) runmax[i] = -1e30f;

    for (int t = 0; t < 16; ++t) {
        if (t < 15) {
            const uint32_t dstHi = sb + OFF_A + ((t + 1) & 1) * (2 * A_STAGE);
            const uint32_t dstLo = dstHi + A_STAGE;
            const int base = (t + 1) * 1024;   // uint4 index
            #pragma unroll
            for (int i = 0; i < 4; ++i) {
                const int idx = tid + i * 256;
                const int m = idx >> 4, j = idx & 15;
                CP_ASYNC16(dstHi + m * LDP + j * 16, (const char*)srcHi + (base + idx) * 16);
                CP_ASYNC16(dstLo + m * LDP + j * 16, (const char*)srcLo + (base + idx) * 16);
            }
            CP_COMMIT();
            CP_WAIT(1);
        } else {
            CP_WAIT(0);
        }
        __syncthreads();

        const uint32_t stage = sb + OFF_A + (t & 1) * (2 * A_STAGE);
        const uint32_t aHi0 = stage + aOffHi;
        const uint32_t aLo0 = stage + A_STAGE + aOffHi;

        float d[2][8][4];
        #pragma unroll
        for (int mt = 0; mt < 2; ++mt)
            #pragma unroll
            for (int j = 0; j < 8; ++j)
                #pragma unroll
                for (int c = 0; c < 4; ++c) d[mt][j][c] = 0.0f;

        #pragma unroll
        for (int ks = 0; ks < 8; ++ks) {
            const uint32_t ko = ks * 32;
            uint32_t aH0[4], aH1[4], aL0[4], aL1[4];
            LDSM_X4(aH0[0], aH0[1], aH0[2], aH0[3], aHi0 + ko);
            LDSM_X4(aH1[0], aH1[1], aH1[2], aH1[3], aHi0 + 16 * LDP + ko);
            LDSM_X4(aL0[0], aL0[1], aL0[2], aL0[3], aLo0 + ko);
            LDSM_X4(aL1[0], aL1[1], aL1[2], aL1[3], aLo0 + 16 * LDP + ko);
            #pragma unroll
            for (int j = 0; j < 4; ++j) {
                uint32_t bH[4], bL[4];
                LDSM_X4(bH[0], bH[1], bH[2], bH[3], bHi0 + j * (16 * LDP) + ko);
                LDSM_X4(bL[0], bL[1], bL[2], bL[3], bLo0 + j * (16 * LDP) + ko);
                mma_bf16(d[0][2 * j],     aH0, bH);
                mma_bf16(d[1][2 * j],     aH1, bH);
                mma_bf16(d[0][2 * j + 1], aH0, bH + 2);
                mma_bf16(d[1][2 * j + 1], aH1, bH + 2);
                mma_bf16(d[0][2 * j],     aH0, bL);
                mma_bf16(d[1][2 * j],     aH1, bL);
                mma_bf16(d[0][2 * j + 1], aH0, bL + 2);
                mma_bf16(d[1][2 * j + 1], aH1, bL + 2);
                mma_bf16(d[0][2 * j],     aL0, bH);
                mma_bf16(d[1][2 * j],     aL1, bH);
                mma_bf16(d[0][2 * j + 1], aL0, bH + 2);
                mma_bf16(d[1][2 * j + 1], aL1, bH + 2);
            }
        }

        #pragma unroll
        for (int j = 0; j < 8; ++j)
            #pragma unroll
            for (int c = 0; c < 2; ++c) {
                float m = fmaxf(fmaxf(d[0][j][c], d[0][j][c + 2]),
                                fmaxf(d[1][j][c], d[1][j][c + 2]));
                runmax[j * 2 + c] = fmaxf(runmax[j * 2 + c], m);
            }
        __syncthreads();
    }

    // Cross-lane row reduction (row varies with lane bits 2..4)
    #pragma unroll
    for (int i = 0; i < 16; ++i) {
        float v = runmax[i];
        v = fmaxf(v, __shfl_xor_sync(0xffffffffu, v, 4));
        v = fmaxf(v, __shfl_xor_sync(0xffffffffu, v, 8));
        v = fmaxf(v, __shfl_xor_sync(0xffffffffu, v, 16));
        runmax[i] = v;
    }
    if (lane < 4) {
        #pragma unroll
        for (int j = 0; j < 8; ++j)
            #pragma unroll
            for (int c = 0; c < 2; ++c)
                scratch[wm * 256 + wn * 64 + j * 8 + lane * 2 + c] = runmax[j * 2 + c];
    }
    __syncthreads();
    {
        float m = fmaxf(scratch[tid], scratch[256 + tid]);
        g_G[b * 1024 + colBase + tid] = fmaxf(m + b3s[tid], 0.0f);
    }
}

// ---------------------------------------------------------------------------
// Head GEMMs: C = act(A @ B + bias). 32x64 tile, cp.async double-buffered.
// ---------------------------------------------------------------------------
#define HD_AS 2176    // 32*68 floats
#define HD_BS 4096    // 64*64 floats
#define HD_STAGE (HD_AS + HD_BS)
#define HD_SMEM (2 * HD_STAGE * 4)

__device__ __forceinline__ void hd_load_chunk(
    uint32_t as, uint32_t bs,
    const float* __restrict__ A, const float* __restrict__ B,
    int rowBase, int colBase, int K, int ldb, int k0, int tid)
{
    #pragma unroll
    for (int i = 0; i < 2; ++i) {
        const int idx = tid + i * 256;
        const int r = idx >> 4, k = (idx & 15) * 4;
        CP_ASYNC16(as + (r * 68 + k) * 4, A + (size_t)(rowBase + r) * K + k0 + k);
    }
    #pragma unroll
    for (int i = 0; i < 4; ++i) {
        const int idx = tid + i * 256;
        const int r = idx >> 4, c = (idx & 15) * 4;
        CP_ASYNC16(bs + (r * 64 + c) * 4, B + (size_t)(k0 + r) * ldb + colBase + c);
    }
}

__device__ __forceinline__ void head_gemm_32(
    const float* __restrict__ A, const float* __restrict__ B,
    const float* __restrict__ bias, float* __restrict__ C,
    int K, int ldb, bool relu)
{
    float* sm = (float*)smem_raw;
    const uint32_t sb = smem_u32(sm);
    const int tid = threadIdx.x;
    const int tx = tid & 15, ty = tid >> 4;
    const int rowBase = blockIdx.x * 32;
    const int colBase = blockIdx.y * 64;
    const int nChunks = K >> 6;

    hd_load_chunk(sb, sb + HD_AS * 4, A, B, rowBase, colBase, K, ldb, 0, tid);
    CP_COMMIT();

    float acc[2][4];
    #pragma unroll
    for (int p = 0; p < 2; ++p)
        #pragma unroll
        for (int c = 0; c < 4; ++c) acc[p][c] = 0.0f;

    for (int ch = 0; ch < nChunks; ++ch) {
        if (ch + 1 < nChunks) {
            const uint32_t as = sb + ((ch + 1) & 1) * HD_STAGE * 4;
            hd_load_chunk(as, as + HD_AS * 4, A, B, rowBase, colBase, K, ldb, (ch + 1) * 64, tid);
            CP_COMMIT();
            CP_WAIT(1);
        } else {
            CP_WAIT(0);
        }
        __syncthreads();

        const float* As = sm + (ch & 1) * HD_STAGE;
        const float* Bs = As + HD_AS;

        #pragma unroll 16
        for (int k = 0; k < 64; ++k) {
            const float4 wv = *(const float4*)(Bs + k * 64 + tx * 4);
            const float a0 = As[(ty * 2 + 0) * 68 + k];
            const float a1 = As[(ty * 2 + 1) * 68 + k];
            acc[0][0] = fmaf(a0, wv.x, acc[0][0]); acc[0][1] = fmaf(a0, wv.y, acc[0][1]);
            acc[0][2] = fmaf(a0, wv.z, acc[0][2]); acc[0][3] = fmaf(a0, wv.w, acc[0][3]);
            acc[1][0] = fmaf(a1, wv.x, acc[1][0]); acc[1][1] = fmaf(a1, wv.y, acc[1][1]);
            acc[1][2] = fmaf(a1, wv.z, acc[1][2]); acc[1][3] = fmaf(a1, wv.w, acc[1][3]);
        }
        __syncthreads();
    }

    #pragma unroll
    for (int p = 0; p < 2; ++p) {
        #pragma unroll
        for (int c = 0; c < 4; ++c) {
            float v = acc[p][c] + bias[colBase + tx * 4 + c];
            if (relu) v = fmaxf(v, 0.0f);
            C[(size_t)(rowBase + ty * 2 + p) * ldb + colBase + tx * 4 + c] = v;
        }
    }
}

__global__ void k3_head1(const float* __restrict__ Wh1, const float* __restrict__ bh1) {
    head_gemm_32(g_G, Wh1, bh1, g_Z1, 1024, 512, true);
}
__global__ void k4_head2(const float* __restrict__ Wh2, const float* __restrict__ bh2) {
    head_gemm_32(g_Z1, Wh2, bh2, g_Z2, 512, 256, true);
}

// ---------------------------------------------------------------------------
// K5: raw = Z2 @ Wh3 + bh3 — warp per output, shfl reduce.
// ---------------------------------------------------------------------------
__global__ void k5_raw(const float* __restrict__ Wh3, const float* __restrict__ bh3)
{
    const int g = blockIdx.x * 8 + (threadIdx.x >> 5);
    if (g >= BATCH * 9) return;
    const int lane = threadIdx.x & 31;
    const int b = g / 9, j = g % 9;
    const float* z = g_Z2 + b * 256;
    float acc = 0.0f;
    #pragma unroll
    for (int i = 0; i < 8; ++i) {
        const int k = lane + i * 32;
        acc = fmaf(z[k], Wh3[k * 9 + j], acc);
    }
    #pragma unroll
    for (int off = 16; off > 0; off >>= 1)
        acc += __shfl_xor_sync(0xffffffffu, acc, off);
    if (lane == 0) g_RAW[g] = acc + bh3[j];
}

// ---------------------------------------------------------------------------
// K6: SVD projection onto SO(3). One thread per 3x3 matrix.
// ---------------------------------------------------------------------------
__device__ __forceinline__ void jrot(float A[3][3], float V[3][3], int p, int q)
{
    float apq = A[p][q];
    if (fabsf(apq) < 1e-20f) return;
    float tau = (A[q][q] - A[p][p]) / (2.0f * apq);
    float t = copysignf(1.0f, tau) / (fabsf(tau) + sqrtf(1.0f + tau * tau));
    float c = 1.0f / sqrtf(1.0f + t * t);
    float s = t * c;
    for (int r = 0; r < 3; ++r) {
        float arp = A[r][p], arq = A[r][q];
        A[r][p] = c * arp - s * arq;
        A[r][q] = s * arp + c * arq;
    }
    for (int r = 0; r < 3; ++r) {
        float apr = A[p][r], aqr = A[q][r];
        A[p][r] = c * apr - s * aqr;
        A[q][r] = s * apr + c * aqr;
    }
    for (int r = 0; r < 3; ++r) {
        float vrp = V[r][p], vrq = V[r][q];
        V[r][p] = c * vrp - s * vrq;
        V[r][q] = s * vrp + c * vrq;
    }
}

__global__ void k6_svd(float* __restrict__ out)
{
    int i = blockIdx.x * 32 + threadIdx.x;
    if (i >= BATCH) return;

    float M[3][3];
    for (int r = 0; r < 3; ++r)
        for (int c = 0; c < 3; ++c)
            M[r][c] = g_RAW[i * 9 + r * 3 + c];

    float A[3][3], V[3][3];
    for (int r = 0; r < 3; ++r)
        for (int c = 0; c < 3; ++c) {
            A[r][c] = M[0][r] * M[0][c] + M[1][r] * M[1][c] + M[2][r] * M[2][c];
            V[r][c] = (r == c) ? 1.0f : 0.0f;
        }

    for (int sweep = 0; sweep < 12; ++sweep) {
        jrot(A, V, 0, 1);
        jrot(A, V, 0, 2);
        jrot(A, V, 1, 2);
    }

    float e0 = A[0][0], e1 = A[1][1], e2 = A[2][2];
    int i0 = 0, i1 = 1, i2 = 2;
    if (e0 < e1) { float t = e0; e0 = e1; e1 = t; int ti = i0; i0 = i1; i1 = ti; }
    if (e0 < e2) { float t = e0; e0 = e2; e2 = t; int ti = i0; i0 = i2; i2 = ti; }
    if (e1 < e2) { float t = e1; e1 = e2; e2 = t; int ti = i1; i1 = i2; i2 = ti; }

    float v1[3], v2[3], v3[3];
    for (int r = 0; r < 3; ++r) { v1[r] = V[r][i0]; v2[r] = V[r][i1]; v3[r] = V[r][i2]; }

    float detV = v1[0] * (v2[1] * v3[2] - v2[2] * v3[1])
               - v1[1] * (v2[0] * v3[2] - v2[2] * v3[0])
               + v1[2] * (v2[0] * v3[1] - v2[1] * v3[0]);

    float w1[3], w2[3];
    for (int r = 0; r < 3; ++r) {
        w1[r] = M[r][0] * v1[0] + M[r][1] * v1[1] + M[r][2] * v1[2];
        w2[r] = M[r][0] * v2[0] + M[r][1] * v2[1] + M[r][2] * v2[2];
    }
    float n1 = sqrtf(w1[0] * w1[0] + w1[1] * w1[1] + w1[2] * w1[2] + 1e-30f);
    float u1[3] = { w1[0] / n1, w1[1] / n1, w1[2] / n1 };
    float d12 = u1[0] * w2[0] + u1[1] * w2[1] + u1[2] * w2[2];
    for (int r = 0; r < 3; ++r) w2[r] -= d12 * u1[r];
    float n2 = sqrtf(w2[0] * w2[0] + w2[1] * w2[1] + w2[2] * w2[2] + 1e-30f);
    float u2[3] = { w2[0] / n2, w2[1] / n2, w2[2] / n2 };
    float u3[3] = { u1[1] * u2[2] - u1[2] * u2[1],
                    u1[2] * u2[0] - u1[0] * u2[2],
                    u1[0] * u2[1] - u1[1] * u2[0] };
    if (detV < 0.0f) { u3[0] = -u3[0]; u3[1] = -u3[1]; u3[2] = -u3[2]; }

    for (int r = 0; r < 3; ++r)
        for (int c = 0; c < 3; ++c)
            out[i * 9 + r * 3 + c] = u1[r] * v1[c] + u2[r] * v2[c] + u3[r] * v3[c];
}

// ---------------------------------------------------------------------------
extern "C" void kernel_launch(void* const* d_in, const int* in_sizes, int n_in,
                              void* d_out, int out_size)
{
    const float* x   = (const float*)d_in[0];
    const float* W1  = (const float*)d_in[1];
    const float* b1  = (const float*)d_in[2];
    const float* W2  = (const float*)d_in[3];
    const float* b2  = (const float*)d_in[4];
    const float* W3  = (const float*)d_in[5];
    const float* b3  = (const float*)d_in[6];
    const float* Wh1 = (const float*)d_in[7];
    const float* bh1 = (const float*)d_in[8];
    const float* Wh2 = (const float*)d_in[9];
    const float* bh2 = (const float*)d_in[10];
    const float* Wh3 = (const float*)d_in[11];
    const float* bh3 = (const float*)d_in[12];
    float* out = (float*)d_out;

    cudaFuncSetAttribute(k1_point_mlp,    cudaFuncAttributeMaxDynamicSharedMemorySize, K1_SMEM);
    cudaFuncSetAttribute(k2_gemm_max_mma, cudaFuncAttributeMaxDynamicSharedMemorySize, K2_SMEM);
    cudaFuncSetAttribute(k3_head1,        cudaFuncAttributeMaxDynamicSharedMemorySize, HD_SMEM);
    cudaFuncSetAttribute(k4_head2,        cudaFuncAttributeMaxDynamicSharedMemorySize, HD_SMEM);

    k1_point_mlp<<<2048, 512, K1_SMEM>>>(x, W1, b1, W2, b2);
    k2_gemm_max_mma<<<dim3(4, 256), 256, K2_SMEM>>>(W3, b3);
    k3_head1<<<dim3(8, 8), 256, HD_SMEM>>>(Wh1, bh1);
    k4_head2<<<dim3(8, 4), 256, HD_SMEM>>>(Wh2, bh2);
    k5_raw<<<288, 256>>>(Wh3, bh3);
    k6_svd<<<8, 32>>>(out);

    (void)in_sizes; (void)n_in; (void)out_size;
}

// round 8
// speedup vs baseline: 4.6391x; 1.6679x over previous
#include <cuda_runtime.h>
#include <cuda_bf16.h>
#include <math.h>
#include <cstdint>

#define BATCH 256
#define NPTS  1024

// Scratch (device globals — allocation-free contract)
__device__ __nv_bfloat16 g_H2hi[BATCH * NPTS * 128];   // 64 MB
__device__ __nv_bfloat16 g_H2lo[BATCH * NPTS * 128];   // 64 MB
__device__ unsigned g_AMAX[BATCH * 1024];
__device__ float g_G[BATCH * 1024];
__device__ float g_Z1[BATCH * 512];
__device__ float g_Z2[BATCH * 256];
__device__ float g_RAW[BATCH * 9];

extern __shared__ char smem_raw[];

__device__ __forceinline__ uint32_t smem_u32(const void* p) {
    uint32_t a;
    asm("{ .reg .u64 t; cvta.to.shared.u64 t, %1; cvt.u32.u64 %0, t; }" : "=r"(a) : "l"(p));
    return a;
}

#define LDSM_X4(r0, r1, r2, r3, addr) \
    asm volatile("ldmatrix.sync.aligned.m8n8.x4.shared.b16 {%0,%1,%2,%3}, [%4];" \
                 : "=r"(r0), "=r"(r1), "=r"(r2), "=r"(r3) : "r"(addr))

__device__ __forceinline__ void mma_bf16(float* d, const uint32_t* a, const uint32_t* b) {
    asm volatile("mma.sync.aligned.m16n8k16.row.col.f32.bf16.bf16.f32 "
                 "{%0,%1,%2,%3},{%4,%5,%6,%7},{%8,%9},{%0,%1,%2,%3};"
                 : "+f"(d[0]), "+f"(d[1]), "+f"(d[2]), "+f"(d[3])
                 : "r"(a[0]), "r"(a[1]), "r"(a[2]), "r"(a[3]), "r"(b[0]), "r"(b[1]));
}

__device__ __forceinline__ uint32_t bf2u(__nv_bfloat162 v) {
    uint32_t u; *(__nv_bfloat162*)&u = v; return u;
}

#define CP_ASYNC16(dst, src) \
    asm volatile("cp.async.cg.shared.global [%0], [%1], 16;" :: "r"(dst), "l"(src))
#define CP_COMMIT() asm volatile("cp.async.commit_group;" ::: "memory")
#define CP_WAIT(n)  asm volatile("cp.async.wait_group %0;" :: "n"(n) : "memory")

// ---------------------------------------------------------------------------
// K1: per-point MLP 3 -> 64 (scalar) -> 128 (HMMA, 3-combo hi/lo bf16),
// fused bias+ReLU+split epilogue, writes g_H2hi/g_H2lo. (unchanged)
// ---------------------------------------------------------------------------
#define K1_LDP 144
#define K1_A_HI 0
#define K1_A_LO 18432
#define K1_B_HI 36864
#define K1_B_LO 55296
#define K1_W1S  73728
#define K1_B1S  74496
#define K1_B2S  74752
#define K1_SMEM 75264

__global__ void __launch_bounds__(512, 1) k1_point_mlp(
    const float* __restrict__ x,
    const float* __restrict__ W1, const float* __restrict__ b1,
    const float* __restrict__ W2, const float* __restrict__ b2)
{
    char* sm = smem_raw;
    const uint32_t sb = smem_u32(sm);
    const int tid = threadIdx.x, lane = tid & 31, w = tid >> 5;
    const int wm = w & 3, wn = w >> 2;
    float* W1s = (float*)(sm + K1_W1S);
    float* b1s = (float*)(sm + K1_B1S);
    float* b2s = (float*)(sm + K1_B2S);

    for (int i = tid; i < 8192; i += 512) {
        const int n = i & 127, k = i >> 7;
        const float v = W2[k * 128 + n];
        const __nv_bfloat16 h = __float2bfloat16(v);
        const __nv_bfloat16 l = __float2bfloat16(v - __bfloat162float(h));
        *(__nv_bfloat16*)(sm + K1_B_HI + n * K1_LDP + k * 2) = h;
        *(__nv_bfloat16*)(sm + K1_B_LO + n * K1_LDP + k * 2) = l;
    }
    if (tid < 192) W1s[tid] = W1[tid];
    else if (tid >= 256 && tid < 320) b1s[tid - 256] = b1[tid - 256];
    else if (tid >= 384 && tid < 512) b2s[tid - 384] = b2[tid - 384];
    __syncthreads();

    {
        const int pl = tid & 127;
        const int ks = (tid >> 7) * 16;
        const int pg = blockIdx.x * 128 + pl;
        const float x0 = x[pg * 3 + 0];
        const float x1 = x[pg * 3 + 1];
        const float x2 = x[pg * 3 + 2];
        #pragma unroll
        for (int kk = 0; kk < 16; kk += 2) {
            const int k = ks + kk;
            float va = fmaxf(fmaf(x0, W1s[k],     fmaf(x1, W1s[64 + k],     fmaf(x2, W1s[128 + k],     b1s[k]))), 0.0f);
            float vb = fmaxf(fmaf(x0, W1s[k + 1], fmaf(x1, W1s[64 + k + 1], fmaf(x2, W1s[128 + k + 1], b1s[k + 1]))), 0.0f);
            __nv_bfloat162 h = __floats2bfloat162_rn(va, vb);
            __nv_bfloat162 l = __floats2bfloat162_rn(va - __bfloat162float(h.x), vb - __bfloat162float(h.y));
            *(uint32_t*)(sm + K1_A_HI + pl * K1_LDP + k * 2) = bf2u(h);
            *(uint32_t*)(sm + K1_A_LO + pl * K1_LDP + k * 2) = bf2u(l);
        }
    }
    __syncthreads();

    const uint32_t aRow = (uint32_t)(wm * 32 + (lane & 15));
    const uint32_t aCol = (uint32_t)((lane >> 4) * 16);
    const uint32_t aHi0 = sb + K1_A_HI + aRow * K1_LDP + aCol;
    const uint32_t aHi1 = aHi0 + 16 * K1_LDP;
    const uint32_t aLo0 = sb + K1_A_LO + aRow * K1_LDP + aCol;
    const uint32_t aLo1 = aLo0 + 16 * K1_LDP;
    const uint32_t bRow = (uint32_t)(wn * 32 + (lane & 7) + ((lane >> 4) << 3));
    const uint32_t bCol = (uint32_t)(((lane >> 3) & 1) * 16);
    const uint32_t bHi0 = sb + K1_B_HI + bRow * K1_LDP + bCol;
    const uint32_t bLo0 = sb + K1_B_LO + bRow * K1_LDP + bCol;

    float d[2][4][4];
    #pragma unroll
    for (int mt = 0; mt < 2; ++mt)
        #pragma unroll
        for (int j = 0; j < 4; ++j)
            #pragma unroll
            for (int c = 0; c < 4; ++c) d[mt][j][c] = 0.0f;

    #pragma unroll
    for (int ks = 0; ks < 4; ++ks) {
        const uint32_t ko = ks * 32;
        uint32_t aH0[4], aH1[4], aL0[4], aL1[4];
        LDSM_X4(aH0[0], aH0[1], aH0[2], aH0[3], aHi0 + ko);
        LDSM_X4(aH1[0], aH1[1], aH1[2], aH1[3], aHi1 + ko);
        LDSM_X4(aL0[0], aL0[1], aL0[2], aL0[3], aLo0 + ko);
        LDSM_X4(aL1[0], aL1[1], aL1[2], aL1[3], aLo1 + ko);
        #pragma unroll
        for (int j = 0; j < 2; ++j) {
            uint32_t bH[4], bL[4];
            LDSM_X4(bH[0], bH[1], bH[2], bH[3], bHi0 + j * (16 * K1_LDP) + ko);
            LDSM_X4(bL[0], bL[1], bL[2], bL[3], bLo0 + j * (16 * K1_LDP) + ko);
            mma_bf16(d[0][2 * j],     aH0, bH);
            mma_bf16(d[1][2 * j],     aH1, bH);
            mma_bf16(d[0][2 * j + 1], aH0, bH + 2);
            mma_bf16(d[1][2 * j + 1], aH1, bH + 2);
            mma_bf16(d[0][2 * j],     aH0, bL);
            mma_bf16(d[1][2 * j],     aH1, bL);
            mma_bf16(d[0][2 * j + 1], aH0, bL + 2);
            mma_bf16(d[1][2 * j + 1], aH1, bL + 2);
            mma_bf16(d[0][2 * j],     aL0, bH);
            mma_bf16(d[1][2 * j],     aL1, bH);
            mma_bf16(d[0][2 * j + 1], aL0, bH + 2);
            mma_bf16(d[1][2 * j + 1], aL1, bH + 2);
        }
    }

    const int pBase = blockIdx.x * 128;
    #pragma unroll
    for (int mt = 0; mt < 2; ++mt) {
        #pragma unroll
        for (int j = 0; j < 4; ++j) {
            const int col = wn * 32 + j * 8 + (lane & 3) * 2;
            const float bc0 = b2s[col], bc1 = b2s[col + 1];
            #pragma unroll
            for (int rr = 0; rr < 2; ++rr) {
                const int row = pBase + wm * 32 + mt * 16 + (lane >> 2) + rr * 8;
                const float v0 = fmaxf(d[mt][j][rr * 2 + 0] + bc0, 0.0f);
                const float v1 = fmaxf(d[mt][j][rr * 2 + 1] + bc1, 0.0f);
                __nv_bfloat162 h = __floats2bfloat162_rn(v0, v1);
                __nv_bfloat162 l = __floats2bfloat162_rn(v0 - __bfloat162float(h.x), v1 - __bfloat162float(h.y));
                *(uint32_t*)(g_H2hi + (size_t)row * 128 + col) = bf2u(h);
                *(uint32_t*)(g_H2lo + (size_t)row * 128 + col) = bf2u(l);
            }
        }
    }
}

// ---------------------------------------------------------------------------
// K2a: 1-combo bf16 HMMA GEMM + argmax-pool. Writes g_AMAX only.
// 256 threads = 8 warps (2m x 4n), warp tile 32x64, cp.async double-buffered
// 64-row hi-only A tiles; B hi-only. smem 106KB -> 2 CTAs/SM.
// ---------------------------------------------------------------------------
#define LDP 272
#define A_STAGE 17408                 // 64*272
#define OFF_A 0                       // 2 stages (hi only)
#define OFF_B 34816                   // 256*272
#define OFF_SV 104448                 // float[512]
#define OFF_SI 106496                 // uint[512]
#define K2_SMEM 108544

__global__ void __launch_bounds__(256, 2) k2_gemm_amax(const float* __restrict__ W3)
{
    char* sm = smem_raw;
    const uint32_t sb = smem_u32(sm);
    const int tid = threadIdx.x, lane = tid & 31, w = tid >> 5;
    const int wm = w & 1, wn = w >> 1;          // 2m x 4n
    const int b = blockIdx.y;
    const int colBase = blockIdx.x * 256;

    float* sval = (float*)(sm + OFF_SV);
    uint32_t* sidx = (uint32_t*)(sm + OFF_SI);

    const __nv_bfloat16* srcHi = g_H2hi + (size_t)b * NPTS * 128;

    // tile 0 A-hi prefetch (overlaps B conversion fill)
    {
        const uint32_t dst = sb + OFF_A;
        #pragma unroll
        for (int i = 0; i < 4; ++i) {
            const int idx = tid + i * 256;
            const int m = idx >> 4, j = idx & 15;
            CP_ASYNC16(dst + m * LDP + j * 16, (const char*)srcHi + idx * 16);
        }
        CP_COMMIT();
    }

    // B fill: Bs[n][k] = bf16(W3[k][colBase+n]) (hi only)
    for (int idx = tid; idx < 32768; idx += 256) {
        const int n = idx & 255, k = idx >> 8;
        *(__nv_bfloat16*)(sm + OFF_B + n * LDP + k * 2) = __float2bfloat16(W3[k * 1024 + colBase + n]);
    }

    const uint32_t aRow = (uint32_t)(wm * 32 + (lane & 15));
    const uint32_t aCol = (uint32_t)((lane >> 4) * 16);
    const uint32_t aOff = aRow * LDP + aCol;
    const uint32_t bRow = (uint32_t)(wn * 64 + (lane & 7) + ((lane >> 4) << 3));
    const uint32_t bColB = (uint32_t)(((lane >> 3) & 1) * 16);
    const uint32_t bH0 = sb + OFF_B + bRow * LDP + bColB;

    float runmax[16];
    uint32_t runidx[16];
    #pragma unroll
    for (int i = 0; i < 16; ++i) { runmax[i] = -1e30f; runidx[i] = 0; }

    for (int t = 0; t < 16; ++t) {
        if (t < 15) {
            const uint32_t dst = sb + OFF_A + ((t + 1) & 1) * A_STAGE;
            const int base = (t + 1) * 1024;
            #pragma unroll
            for (int i = 0; i < 4; ++i) {
                const int idx = tid + i * 256;
                const int m = idx >> 4, j = idx & 15;
                CP_ASYNC16(dst + m * LDP + j * 16, (const char*)srcHi + (base + idx) * 16);
            }
            CP_COMMIT();
            CP_WAIT(1);
        } else {
            CP_WAIT(0);
        }
        __syncthreads();

        const uint32_t aHi0 = sb + OFF_A + (t & 1) * A_STAGE + aOff;

        float d[2][8][4];
        #pragma unroll
        for (int mt = 0; mt < 2; ++mt)
            #pragma unroll
            for (int j = 0; j < 8; ++j)
                #pragma unroll
                for (int c = 0; c < 4; ++c) d[mt][j][c] = 0.0f;

        #pragma unroll
        for (int ks = 0; ks < 8; ++ks) {
            const uint32_t ko = ks * 32;
            uint32_t aH0[4], aH1[4];
            LDSM_X4(aH0[0], aH0[1], aH0[2], aH0[3], aHi0 + ko);
            LDSM_X4(aH1[0], aH1[1], aH1[2], aH1[3], aHi0 + 16 * LDP + ko);
            #pragma unroll
            for (int j = 0; j < 4; ++j) {
                uint32_t bH[4];
                LDSM_X4(bH[0], bH[1], bH[2], bH[3], bH0 + j * (16 * LDP) + ko);
                mma_bf16(d[0][2 * j],     aH0, bH);
                mma_bf16(d[1][2 * j],     aH1, bH);
                mma_bf16(d[0][2 * j + 1], aH0, bH + 2);
                mma_bf16(d[1][2 * j + 1], aH1, bH + 2);
            }
        }

        // fold (max, argmax): frag rows = rbase + {0,8,16,24}
        const uint32_t rbase = (uint32_t)(t * 64 + wm * 32 + (lane >> 2));
        #pragma unroll
        for (int f = 0; f < 8; ++f) {
            #pragma unroll
            for (int cc = 0; cc < 2; ++cc) {
                const int e = f * 2 + cc;
                const float v0 = d[0][f][cc],     v1 = d[0][f][cc + 2];
                const float v2 = d[1][f][cc],     v3 = d[1][f][cc + 2];
                if (v0 > runmax[e]) { runmax[e] = v0; runidx[e] = rbase; }
                if (v1 > runmax[e]) { runmax[e] = v1; runidx[e] = rbase + 8; }
                if (v2 > runmax[e]) { runmax[e] = v2; runidx[e] = rbase + 16; }
                if (v3 > runmax[e]) { runmax[e] = v3; runidx[e] = rbase + 24; }
            }
        }
        __syncthreads();
    }

    // cross-lane (row lives in lane bits 2..4): reduce val+idx
    #pragma unroll
    for (int e = 0; e < 16; ++e) {
        #pragma unroll
        for (int off = 4; off <= 16; off <<= 1) {
            const float ov = __shfl_xor_sync(0xffffffffu, runmax[e], off);
            const uint32_t oi = __shfl_xor_sync(0xffffffffu, runidx[e], off);
            if (ov > runmax[e]) { runmax[e] = ov; runidx[e] = oi; }
        }
    }
    if (lane < 4) {
        #pragma unroll
        for (int f = 0; f < 8; ++f) {
            #pragma unroll
            for (int cc = 0; cc < 2; ++cc) {
                const int cl = wn * 64 + f * 8 + lane * 2 + cc;
                sval[wm * 256 + cl] = runmax[f * 2 + cc];
                sidx[wm * 256 + cl] = runidx[f * 2 + cc];
            }
        }
    }
    __syncthreads();
    {
        const float v0 = sval[tid], v1 = sval[256 + tid];
        g_AMAX[b * 1024 + colBase + tid] = (v1 > v0) ? sidx[256 + tid] : sidx[tid];
    }
}

// ---------------------------------------------------------------------------
// K2b: exact fixup. g[b][col] = relu(fp32 dot(h2[argmax], W3[:,col]) + b3).
// h2 reconstructed as hi+lo (~2^-18 accurate).
// ---------------------------------------------------------------------------
__global__ void __launch_bounds__(256) k2_fixup(const float* __restrict__ W3,
                                                const float* __restrict__ b3)
{
    const int tid = threadIdx.x;
    const int b = blockIdx.y;
    const int col = blockIdx.x * 256 + tid;
    const unsigned i = g_AMAX[b * 1024 + col];

    const uint4* hi = (const uint4*)(g_H2hi + ((size_t)b * NPTS + i) * 128);
    const uint4* lo = (const uint4*)(g_H2lo + ((size_t)b * NPTS + i) * 128);

    float acc = 0.0f;
    #pragma unroll
    for (int c = 0; c < 16; ++c) {
        const uint4 h4 = hi[c];
        const uint4 l4 = lo[c];
        const uint32_t hw[4] = {h4.x, h4.y, h4.z, h4.w};
        const uint32_t lw[4] = {l4.x, l4.y, l4.z, l4.w};
        #pragma unroll
        for (int q = 0; q < 4; ++q) {
            const __nv_bfloat162 hh = *(const __nv_bfloat162*)&hw[q];
            const __nv_bfloat162 ll = *(const __nv_bfloat162*)&lw[q];
            const int k = c * 8 + q * 2;
            const float a0 = __bfloat162float(hh.x) + __bfloat162float(ll.x);
            const float a1 = __bfloat162float(hh.y) + __bfloat162float(ll.y);
            acc = fmaf(a0, W3[(size_t)k * 1024 + col], acc);
            acc = fmaf(a1, W3[(size_t)(k + 1) * 1024 + col], acc);
        }
    }
    g_G[b * 1024 + col] = fmaxf(acc + b3[col], 0.0f);
}

// ---------------------------------------------------------------------------
// Head GEMMs: C = act(A @ B + bias). 32x64 tile, cp.async double-buffered.
// ---------------------------------------------------------------------------
#define HD_AS 2176    // 32*68 floats
#define HD_BS 4096    // 64*64 floats
#define HD_STAGE (HD_AS + HD_BS)
#define HD_SMEM (2 * HD_STAGE * 4)

__device__ __forceinline__ void hd_load_chunk(
    uint32_t as, uint32_t bs,
    const float* __restrict__ A, const float* __restrict__ B,
    int rowBase, int colBase, int K, int ldb, int k0, int tid)
{
    #pragma unroll
    for (int i = 0; i < 2; ++i) {
        const int idx = tid + i * 256;
        const int r = idx >> 4, k = (idx & 15) * 4;
        CP_ASYNC16(as + (r * 68 + k) * 4, A + (size_t)(rowBase + r) * K + k0 + k);
    }
    #pragma unroll
    for (int i = 0; i < 4; ++i) {
        const int idx = tid + i * 256;
        const int r = idx >> 4, c = (idx & 15) * 4;
        CP_ASYNC16(bs + (r * 64 + c) * 4, B + (size_t)(k0 + r) * ldb + colBase + c);
    }
}

__device__ __forceinline__ void head_gemm_32(
    const float* __restrict__ A, const float* __restrict__ B,
    const float* __restrict__ bias, float* __restrict__ C,
    int K, int ldb, bool relu)
{
    float* sm = (float*)smem_raw;
    const uint32_t sb = smem_u32(sm);
    const int tid = threadIdx.x;
    const int tx = tid & 15, ty = tid >> 4;
    const int rowBase = blockIdx.x * 32;
    const int colBase = blockIdx.y * 64;
    const int nChunks = K >> 6;

    hd_load_chunk(sb, sb + HD_AS * 4, A, B, rowBase, colBase, K, ldb, 0, tid);
    CP_COMMIT();

    float acc[2][4];
    #pragma unroll
    for (int p = 0; p < 2; ++p)
        #pragma unroll
        for (int c = 0; c < 4; ++c) acc[p][c] = 0.0f;

    for (int ch = 0; ch < nChunks; ++ch) {
        if (ch + 1 < nChunks) {
            const uint32_t as = sb + ((ch + 1) & 1) * HD_STAGE * 4;
            hd_load_chunk(as, as + HD_AS * 4, A, B, rowBase, colBase, K, ldb, (ch + 1) * 64, tid);
            CP_COMMIT();
            CP_WAIT(1);
        } else {
            CP_WAIT(0);
        }
        __syncthreads();

        const float* As = sm + (ch & 1) * HD_STAGE;
        const float* Bs = As + HD_AS;

        #pragma unroll 16
        for (int k = 0; k < 64; ++k) {
            const float4 wv = *(const float4*)(Bs + k * 64 + tx * 4);
            const float a0 = As[(ty * 2 + 0) * 68 + k];
            const float a1 = As[(ty * 2 + 1) * 68 + k];
            acc[0][0] = fmaf(a0, wv.x, acc[0][0]); acc[0][1] = fmaf(a0, wv.y, acc[0][1]);
            acc[0][2] = fmaf(a0, wv.z, acc[0][2]); acc[0][3] = fmaf(a0, wv.w, acc[0][3]);
            acc[1][0] = fmaf(a1, wv.x, acc[1][0]); acc[1][1] = fmaf(a1, wv.y, acc[1][1]);
            acc[1][2] = fmaf(a1, wv.z, acc[1][2]); acc[1][3] = fmaf(a1, wv.w, acc[1][3]);
        }
        __syncthreads();
    }

    #pragma unroll
    for (int p = 0; p < 2; ++p) {
        #pragma unroll
        for (int c = 0; c < 4; ++c) {
            float v = acc[p][c] + bias[colBase + tx * 4 + c];
            if (relu) v = fmaxf(v, 0.0f);
            C[(size_t)(rowBase + ty * 2 + p) * ldb + colBase + tx * 4 + c] = v;
        }
    }
}

__global__ void k3_head1(const float* __restrict__ Wh1, const float* __restrict__ bh1) {
    head_gemm_32(g_G, Wh1, bh1, g_Z1, 1024, 512, true);
}
__global__ void k4_head2(const float* __restrict__ Wh2, const float* __restrict__ bh2) {
    head_gemm_32(g_Z1, Wh2, bh2, g_Z2, 512, 256, true);
}

// ---------------------------------------------------------------------------
// K5: raw = Z2 @ Wh3 + bh3 — warp per output, shfl reduce.
// ---------------------------------------------------------------------------
__global__ void k5_raw(const float* __restrict__ Wh3, const float* __restrict__ bh3)
{
    const int g = blockIdx.x * 8 + (threadIdx.x >> 5);
    if (g >= BATCH * 9) return;
    const int lane = threadIdx.x & 31;
    const int b = g / 9, j = g % 9;
    const float* z = g_Z2 + b * 256;
    float acc = 0.0f;
    #pragma unroll
    for (int i = 0; i < 8; ++i) {
        const int k = lane + i * 32;
        acc = fmaf(z[k], Wh3[k * 9 + j], acc);
    }
    #pragma unroll
    for (int off = 16; off > 0; off >>= 1)
        acc += __shfl_xor_sync(0xffffffffu, acc, off);
    if (lane == 0) g_RAW[g] = acc + bh3[j];
}

// ---------------------------------------------------------------------------
// K6: SVD projection onto SO(3). One thread per 3x3 matrix.
// ---------------------------------------------------------------------------
__device__ __forceinline__ void jrot(float A[3][3], float V[3][3], int p, int q)
{
    float apq = A[p][q];
    if (fabsf(apq) < 1e-20f) return;
    float tau = (A[q][q] - A[p][p]) / (2.0f * apq);
    float t = copysignf(1.0f, tau) / (fabsf(tau) + sqrtf(1.0f + tau * tau));
    float c = 1.0f / sqrtf(1.0f + t * t);
    float s = t * c;
    for (int r = 0; r < 3; ++r) {
        float arp = A[r][p], arq = A[r][q];
        A[r][p] = c * arp - s * arq;
        A[r][q] = s * arp + c * arq;
    }
    for (int r = 0; r < 3; ++r) {
        float apr = A[p][r], aqr = A[q][r];
        A[p][r] = c * apr - s * aqr;
        A[q][r] = s * apr + c * aqr;
    }
    for (int r = 0; r < 3; ++r) {
        float vrp = V[r][p], vrq = V[r][q];
        V[r][p] = c * vrp - s * vrq;
        V[r][q] = s * vrp + c * vrq;
    }
}

__global__ void k6_svd(float* __restrict__ out)
{
    int i = blockIdx.x * 32 + threadIdx.x;
    if (i >= BATCH) return;

    float M[3][3];
    for (int r = 0; r < 3; ++r)
        for (int c = 0; c < 3; ++c)
            M[r][c] = g_RAW[i * 9 + r * 3 + c];

    float A[3][3], V[3][3];
    for (int r = 0; r < 3; ++r)
        for (int c = 0; c < 3; ++c) {
            A[r][c] = M[0][r] * M[0][c] + M[1][r] * M[1][c] + M[2][r] * M[2][c];
            V[r][c] = (r == c) ? 1.0f : 0.0f;
        }

    for (int sweep = 0; sweep < 12; ++sweep) {
        jrot(A, V, 0, 1);
        jrot(A, V, 0, 2);
        jrot(A, V, 1, 2);
    }

    float e0 = A[0][0], e1 = A[1][1], e2 = A[2][2];
    int i0 = 0, i1 = 1, i2 = 2;
    if (e0 < e1) { float t = e0; e0 = e1; e1 = t; int ti = i0; i0 = i1; i1 = ti; }
    if (e0 < e2) { float t = e0; e0 = e2; e2 = t; int ti = i0; i0 = i2; i2 = ti; }
    if (e1 < e2) { float t = e1; e1 = e2; e2 = t; int ti = i1; i1 = i2; i2 = ti; }

    float v1[3], v2[3], v3[3];
    for (int r = 0; r < 3; ++r) { v1[r] = V[r][i0]; v2[r] = V[r][i1]; v3[r] = V[r][i2]; }

    float detV = v1[0] * (v2[1] * v3[2] - v2[2] * v3[1])
               - v1[1] * (v2[0] * v3[2] - v2[2] * v3[0])
               + v1[2] * (v2[0] * v3[1] - v2[1] * v3[0]);

    float w1[3], w2[3];
    for (int r = 0; r < 3; ++r) {
        w1[r] = M[r][0] * v1[0] + M[r][1] * v1[1] + M[r][2] * v1[2];
        w2[r] = M[r][0] * v2[0] + M[r][1] * v2[1] + M[r][2] * v2[2];
    }
    float n1 = sqrtf(w1[0] * w1[0] + w1[1] * w1[1] + w1[2] * w1[2] + 1e-30f);
    float u1[3] = { w1[0] / n1, w1[1] / n1, w1[2] / n1 };
    float d12 = u1[0] * w2[0] + u1[1] * w2[1] + u1[2] * w2[2];
    for (int r = 0; r < 3; ++r) w2[r] -= d12 * u1[r];
    float n2 = sqrtf(w2[0] * w2[0] + w2[1] * w2[1] + w2[2] * w2[2] + 1e-30f);
    float u2[3] = { w2[0] / n2, w2[1] / n2, w2[2] / n2 };
    float u3[3] = { u1[1] * u2[2] - u1[2] * u2[1],
                    u1[2] * u2[0] - u1[0] * u2[2],
                    u1[0] * u2[1] - u1[1] * u2[0] };
    if (detV < 0.0f) { u3[0] = -u3[0]; u3[1] = -u3[1]; u3[2] = -u3[2]; }

    for (int r = 0; r < 3; ++r)
        for (int c = 0; c < 3; ++c)
            out[i * 9 + r * 3 + c] = u1[r] * v1[c] + u2[r] * v2[c] + u3[r] * v3[c];
}

// ---------------------------------------------------------------------------
extern "C" void kernel_launch(void* const* d_in, const int* in_sizes, int n_in,
                              void* d_out, int out_size)
{
    const float* x   = (const float*)d_in[0];
    const float* W1  = (const float*)d_in[1];
    const float* b1  = (const float*)d_in[2];
    const float* W2  = (const float*)d_in[3];
    const float* b2  = (const float*)d_in[4];
    const float* W3  = (const float*)d_in[5];
    const float* b3  = (const float*)d_in[6];
    const float* Wh1 = (const float*)d_in[7];
    const float* bh1 = (const float*)d_in[8];
    const float* Wh2 = (const float*)d_in[9];
    const float* bh2 = (const float*)d_in[10];
    const float* Wh3 = (const float*)d_in[11];
    const float* bh3 = (const float*)d_in[12];
    float* out = (float*)d_out;

    cudaFuncSetAttribute(k1_point_mlp,  cudaFuncAttributeMaxDynamicSharedMemorySize, K1_SMEM);
    cudaFuncSetAttribute(k2_gemm_amax,  cudaFuncAttributeMaxDynamicSharedMemorySize, K2_SMEM);
    cudaFuncSetAttribute(k3_head1,      cudaFuncAttributeMaxDynamicSharedMemorySize, HD_SMEM);
    cudaFuncSetAttribute(k4_head2,      cudaFuncAttributeMaxDynamicSharedMemorySize, HD_SMEM);

    k1_point_mlp<<<2048, 512, K1_SMEM>>>(x, W1, b1, W2, b2);
    k2_gemm_amax<<<dim3(4, 256), 256, K2_SMEM>>>(W3);
    k2_fixup<<<dim3(4, 256), 256>>>(W3, b3);
    k3_head1<<<dim3(8, 8), 256, HD_SMEM>>>(Wh1, bh1);
    k4_head2<<<dim3(8, 4), 256, HD_SMEM>>>(Wh2, bh2);
    k5_raw<<<288, 256>>>(Wh3, bh3);
    k6_svd<<<8, 32>>>(out);

    (void)in_sizes; (void)n_in; (void)out_size;
}

// round 9
// speedup vs baseline: 4.6861x; 1.0101x over previous
#include <cuda_runtime.h>
#include <cuda_fp16.h>
#include <math.h>
#include <cstdint>

#define BATCH 256
#define NPTS  1024

// Scratch (device globals — allocation-free contract)
__device__ __half g_H2hi[BATCH * NPTS * 128];   // 64 MB
__device__ __half g_H2lo[BATCH * NPTS * 128];   // 64 MB
__device__ unsigned g_AMAX[BATCH * 1024];
__device__ float g_G[BATCH * 1024];
__device__ float g_Z1[BATCH * 512];
__device__ float g_Z2[BATCH * 256];
__device__ float g_RAW[BATCH * 9];

extern __shared__ char smem_raw[];

__device__ __forceinline__ uint32_t smem_u32(const void* p) {
    uint32_t a;
    asm("{ .reg .u64 t; cvta.to.shared.u64 t, %1; cvt.u32.u64 %0, t; }" : "=r"(a) : "l"(p));
    return a;
}

#define LDSM_X4(r0, r1, r2, r3, addr) \
    asm volatile("ldmatrix.sync.aligned.m8n8.x4.shared.b16 {%0,%1,%2,%3}, [%4];" \
                 : "=r"(r0), "=r"(r1), "=r"(r2), "=r"(r3) : "r"(addr))

__device__ __forceinline__ void mma_f16(float* d, const uint32_t* a, const uint32_t* b) {
    asm volatile("mma.sync.aligned.m16n8k16.row.col.f32.f16.f16.f32 "
                 "{%0,%1,%2,%3},{%4,%5,%6,%7},{%8,%9},{%0,%1,%2,%3};"
                 : "+f"(d[0]), "+f"(d[1]), "+f"(d[2]), "+f"(d[3])
                 : "r"(a[0]), "r"(a[1]), "r"(a[2]), "r"(a[3]), "r"(b[0]), "r"(b[1]));
}

__device__ __forceinline__ uint32_t h2u(__half2 v) {
    uint32_t u; *(__half2*)&u = v; return u;
}

__device__ __forceinline__ void split2(float va, float vb, uint32_t& hi, uint32_t& lo) {
    __half2 h = __floats2half2_rn(va, vb);
    __half2 l = __floats2half2_rn(va - __half2float(__low2half(h)),
                                  vb - __half2float(__high2half(h)));
    hi = h2u(h); lo = h2u(l);
}

#define CP_ASYNC16(dst, src) \
    asm volatile("cp.async.cg.shared.global [%0], [%1], 16;" :: "r"(dst), "l"(src))
#define CP_COMMIT() asm volatile("cp.async.commit_group;" ::: "memory")
#define CP_WAIT(n)  asm volatile("cp.async.wait_group %0;" :: "n"(n) : "memory")

// ---------------------------------------------------------------------------
// K1: per-point MLP 3 -> 64 (scalar) -> 128 (HMMA fp16 3-combo hi/lo),
// fused bias+ReLU+split epilogue, writes g_H2hi/g_H2lo.
// ---------------------------------------------------------------------------
#define K1_LDP 144
#define K1_A_HI 0
#define K1_A_LO 18432
#define K1_B_HI 36864
#define K1_B_LO 55296
#define K1_W1S  73728
#define K1_B1S  74496
#define K1_B2S  74752
#define K1_SMEM 75264

__global__ void __launch_bounds__(512, 1) k1_point_mlp(
    const float* __restrict__ x,
    const float* __restrict__ W1, const float* __restrict__ b1,
    const float* __restrict__ W2, const float* __restrict__ b2)
{
    char* sm = smem_raw;
    const uint32_t sb = smem_u32(sm);
    const int tid = threadIdx.x, lane = tid & 31, w = tid >> 5;
    const int wm = w & 3, wn = w >> 2;
    float* W1s = (float*)(sm + K1_W1S);
    float* b1s = (float*)(sm + K1_B1S);
    float* b2s = (float*)(sm + K1_B2S);

    for (int i = tid; i < 8192; i += 512) {
        const int n = i & 127, k = i >> 7;
        const float v = W2[k * 128 + n];
        const __half h = __float2half_rn(v);
        const __half l = __float2half_rn(v - __half2float(h));
        *(__half*)(sm + K1_B_HI + n * K1_LDP + k * 2) = h;
        *(__half*)(sm + K1_B_LO + n * K1_LDP + k * 2) = l;
    }
    if (tid < 192) W1s[tid] = W1[tid];
    else if (tid >= 256 && tid < 320) b1s[tid - 256] = b1[tid - 256];
    else if (tid >= 384 && tid < 512) b2s[tid - 384] = b2[tid - 384];
    __syncthreads();

    {
        const int pl = tid & 127;
        const int ks = (tid >> 7) * 16;
        const int pg = blockIdx.x * 128 + pl;
        const float x0 = x[pg * 3 + 0];
        const float x1 = x[pg * 3 + 1];
        const float x2 = x[pg * 3 + 2];
        #pragma unroll
        for (int kk = 0; kk < 16; kk += 2) {
            const int k = ks + kk;
            float va = fmaxf(fmaf(x0, W1s[k],     fmaf(x1, W1s[64 + k],     fmaf(x2, W1s[128 + k],     b1s[k]))), 0.0f);
            float vb = fmaxf(fmaf(x0, W1s[k + 1], fmaf(x1, W1s[64 + k + 1], fmaf(x2, W1s[128 + k + 1], b1s[k + 1]))), 0.0f);
            uint32_t hh, ll;
            split2(va, vb, hh, ll);
            *(uint32_t*)(sm + K1_A_HI + pl * K1_LDP + k * 2) = hh;
            *(uint32_t*)(sm + K1_A_LO + pl * K1_LDP + k * 2) = ll;
        }
    }
    __syncthreads();

    const uint32_t aRow = (uint32_t)(wm * 32 + (lane & 15));
    const uint32_t aCol = (uint32_t)((lane >> 4) * 16);
    const uint32_t aHi0 = sb + K1_A_HI + aRow * K1_LDP + aCol;
    const uint32_t aHi1 = aHi0 + 16 * K1_LDP;
    const uint32_t aLo0 = sb + K1_A_LO + aRow * K1_LDP + aCol;
    const uint32_t aLo1 = aLo0 + 16 * K1_LDP;
    const uint32_t bRow = (uint32_t)(wn * 32 + (lane & 7) + ((lane >> 4) << 3));
    const uint32_t bCol = (uint32_t)(((lane >> 3) & 1) * 16);
    const uint32_t bHi0 = sb + K1_B_HI + bRow * K1_LDP + bCol;
    const uint32_t bLo0 = sb + K1_B_LO + bRow * K1_LDP + bCol;

    float d[2][4][4];
    #pragma unroll
    for (int mt = 0; mt < 2; ++mt)
        #pragma unroll
        for (int j = 0; j < 4; ++j)
            #pragma unroll
            for (int c = 0; c < 4; ++c) d[mt][j][c] = 0.0f;

    #pragma unroll
    for (int ks = 0; ks < 4; ++ks) {
        const uint32_t ko = ks * 32;
        uint32_t aH0[4], aH1[4], aL0[4], aL1[4];
        LDSM_X4(aH0[0], aH0[1], aH0[2], aH0[3], aHi0 + ko);
        LDSM_X4(aH1[0], aH1[1], aH1[2], aH1[3], aHi1 + ko);
        LDSM_X4(aL0[0], aL0[1], aL0[2], aL0[3], aLo0 + ko);
        LDSM_X4(aL1[0], aL1[1], aL1[2], aL1[3], aLo1 + ko);
        #pragma unroll
        for (int j = 0; j < 2; ++j) {
            uint32_t bH[4], bL[4];
            LDSM_X4(bH[0], bH[1], bH[2], bH[3], bHi0 + j * (16 * K1_LDP) + ko);
            LDSM_X4(bL[0], bL[1], bL[2], bL[3], bLo0 + j * (16 * K1_LDP) + ko);
            mma_f16(d[0][2 * j],     aH0, bH);
            mma_f16(d[1][2 * j],     aH1, bH);
            mma_f16(d[0][2 * j + 1], aH0, bH + 2);
            mma_f16(d[1][2 * j + 1], aH1, bH + 2);
            mma_f16(d[0][2 * j],     aH0, bL);
            mma_f16(d[1][2 * j],     aH1, bL);
            mma_f16(d[0][2 * j + 1], aH0, bL + 2);
            mma_f16(d[1][2 * j + 1], aH1, bL + 2);
            mma_f16(d[0][2 * j],     aL0, bH);
            mma_f16(d[1][2 * j],     aL1, bH);
            mma_f16(d[0][2 * j + 1], aL0, bH + 2);
            mma_f16(d[1][2 * j + 1], aL1, bH + 2);
        }
    }

    const int pBase = blockIdx.x * 128;
    #pragma unroll
    for (int mt = 0; mt < 2; ++mt) {
        #pragma unroll
        for (int j = 0; j < 4; ++j) {
            const int col = wn * 32 + j * 8 + (lane & 3) * 2;
            const float bc0 = b2s[col], bc1 = b2s[col + 1];
            #pragma unroll
            for (int rr = 0; rr < 2; ++rr) {
                const int row = pBase + wm * 32 + mt * 16 + (lane >> 2) + rr * 8;
                const float v0 = fmaxf(d[mt][j][rr * 2 + 0] + bc0, 0.0f);
                const float v1 = fmaxf(d[mt][j][rr * 2 + 1] + bc1, 0.0f);
                uint32_t hh, ll;
                split2(v0, v1, hh, ll);
                *(uint32_t*)(g_H2hi + (size_t)row * 128 + col) = hh;
                *(uint32_t*)(g_H2lo + (size_t)row * 128 + col) = ll;
            }
        }
    }
}

// ---------------------------------------------------------------------------
// K2a: 1-combo fp16 HMMA GEMM + argmax-pool. Writes g_AMAX only.
// 256 threads = 8 warps (2m x 4n), warp tile 32x64, cp.async double-buffered
// 64-row hi-only A tiles; B hi-only. smem 106KB -> 2 CTAs/SM.
// ---------------------------------------------------------------------------
#define LDP 272
#define A_STAGE 17408                 // 64*272
#define OFF_A 0                       // 2 stages (hi only)
#define OFF_B 34816                   // 256*272
#define OFF_SV 104448                 // float[512]
#define OFF_SI 106496                 // uint[512]
#define K2_SMEM 108544

__global__ void __launch_bounds__(256, 2) k2_gemm_amax(const float* __restrict__ W3)
{
    char* sm = smem_raw;
    const uint32_t sb = smem_u32(sm);
    const int tid = threadIdx.x, lane = tid & 31, w = tid >> 5;
    const int wm = w & 1, wn = w >> 1;          // 2m x 4n
    const int b = blockIdx.y;
    const int colBase = blockIdx.x * 256;

    float* sval = (float*)(sm + OFF_SV);
    uint32_t* sidx = (uint32_t*)(sm + OFF_SI);

    const __half* srcHi = g_H2hi + (size_t)b * NPTS * 128;

    // tile 0 A-hi prefetch (overlaps B conversion fill)
    {
        const uint32_t dst = sb + OFF_A;
        #pragma unroll
        for (int i = 0; i < 4; ++i) {
            const int idx = tid + i * 256;
            const int m = idx >> 4, j = idx & 15;
            CP_ASYNC16(dst + m * LDP + j * 16, (const char*)srcHi + idx * 16);
        }
        CP_COMMIT();
    }

    // B fill: Bs[n][k] = fp16(W3[k][colBase+n]) (hi only)
    for (int idx = tid; idx < 32768; idx += 256) {
        const int n = idx & 255, k = idx >> 8;
        *(__half*)(sm + OFF_B + n * LDP + k * 2) = __float2half_rn(W3[k * 1024 + colBase + n]);
    }

    const uint32_t aRow = (uint32_t)(wm * 32 + (lane & 15));
    const uint32_t aCol = (uint32_t)((lane >> 4) * 16);
    const uint32_t aOff = aRow * LDP + aCol;
    const uint32_t bRow = (uint32_t)(wn * 64 + (lane & 7) + ((lane >> 4) << 3));
    const uint32_t bColB = (uint32_t)(((lane >> 3) & 1) * 16);
    const uint32_t bH0 = sb + OFF_B + bRow * LDP + bColB;

    float runmax[16];
    uint32_t runidx[16];
    #pragma unroll
    for (int i = 0; i < 16; ++i) { runmax[i] = -1e30f; runidx[i] = 0; }

    for (int t = 0; t < 16; ++t) {
        if (t < 15) {
            const uint32_t dst = sb + OFF_A + ((t + 1) & 1) * A_STAGE;
            const int base = (t + 1) * 1024;
            #pragma unroll
            for (int i = 0; i < 4; ++i) {
                const int idx = tid + i * 256;
                const int m = idx >> 4, j = idx & 15;
                CP_ASYNC16(dst + m * LDP + j * 16, (const char*)srcHi + (base + idx) * 16);
            }
            CP_COMMIT();
            CP_WAIT(1);
        } else {
            CP_WAIT(0);
        }
        __syncthreads();

        const uint32_t aHi0 = sb + OFF_A + (t & 1) * A_STAGE + aOff;

        float d[2][8][4];
        #pragma unroll
        for (int mt = 0; mt < 2; ++mt)
            #pragma unroll
            for (int j = 0; j < 8; ++j)
                #pragma unroll
                for (int c = 0; c < 4; ++c) d[mt][j][c] = 0.0f;

        #pragma unroll
        for (int ks = 0; ks < 8; ++ks) {
            const uint32_t ko = ks * 32;
            uint32_t aH0[4], aH1[4];
            LDSM_X4(aH0[0], aH0[1], aH0[2], aH0[3], aHi0 + ko);
            LDSM_X4(aH1[0], aH1[1], aH1[2], aH1[3], aHi0 + 16 * LDP + ko);
            #pragma unroll
            for (int j = 0; j < 4; ++j) {
                uint32_t bH[4];
                LDSM_X4(bH[0], bH[1], bH[2], bH[3], bH0 + j * (16 * LDP) + ko);
                mma_f16(d[0][2 * j],     aH0, bH);
                mma_f16(d[1][2 * j],     aH1, bH);
                mma_f16(d[0][2 * j + 1], aH0, bH + 2);
                mma_f16(d[1][2 * j + 1], aH1, bH + 2);
            }
        }

        // fold (max, argmax): frag rows = rbase + {0,8,16,24}
        const uint32_t rbase = (uint32_t)(t * 64 + wm * 32 + (lane >> 2));
        #pragma unroll
        for (int f = 0; f < 8; ++f) {
            #pragma unroll
            for (int cc = 0; cc < 2; ++cc) {
                const int e = f * 2 + cc;
                const float v0 = d[0][f][cc],     v1 = d[0][f][cc + 2];
                const float v2 = d[1][f][cc],     v3 = d[1][f][cc + 2];
                if (v0 > runmax[e]) { runmax[e] = v0; runidx[e] = rbase; }
                if (v1 > runmax[e]) { runmax[e] = v1; runidx[e] = rbase + 8; }
                if (v2 > runmax[e]) { runmax[e] = v2; runidx[e] = rbase + 16; }
                if (v3 > runmax[e]) { runmax[e] = v3; runidx[e] = rbase + 24; }
            }
        }
        __syncthreads();
    }

    // cross-lane (row lives in lane bits 2..4): reduce val+idx
    #pragma unroll
    for (int e = 0; e < 16; ++e) {
        #pragma unroll
        for (int off = 4; off <= 16; off <<= 1) {
            const float ov = __shfl_xor_sync(0xffffffffu, runmax[e], off);
            const uint32_t oi = __shfl_xor_sync(0xffffffffu, runidx[e], off);
            if (ov > runmax[e]) { runmax[e] = ov; runidx[e] = oi; }
        }
    }
    if (lane < 4) {
        #pragma unroll
        for (int f = 0; f < 8; ++f) {
            #pragma unroll
            for (int cc = 0; cc < 2; ++cc) {
                const int cl = wn * 64 + f * 8 + lane * 2 + cc;
                sval[wm * 256 + cl] = runmax[f * 2 + cc];
                sidx[wm * 256 + cl] = runidx[f * 2 + cc];
            }
        }
    }
    __syncthreads();
    {
        const float v0 = sval[tid], v1 = sval[256 + tid];
        g_AMAX[b * 1024 + colBase + tid] = (v1 > v0) ? sidx[256 + tid] : sidx[tid];
    }
}

// ---------------------------------------------------------------------------
// K2b: exact fixup. g[b][col] = relu(fp32 dot(h2[argmax], W3[:,col]) + b3).
// h2 reconstructed as hi+lo (~2^-22 accurate with fp16 split).
// ---------------------------------------------------------------------------
__global__ void __launch_bounds__(256) k2_fixup(const float* __restrict__ W3,
                                                const float* __restrict__ b3)
{
    const int tid = threadIdx.x;
    const int b = blockIdx.y;
    const int col = blockIdx.x * 256 + tid;
    const unsigned i = g_AMAX[b * 1024 + col];

    const uint4* hi = (const uint4*)(g_H2hi + ((size_t)b * NPTS + i) * 128);
    const uint4* lo = (const uint4*)(g_H2lo + ((size_t)b * NPTS + i) * 128);

    float acc = 0.0f;
    #pragma unroll
    for (int c = 0; c < 16; ++c) {
        const uint4 h4 = hi[c];
        const uint4 l4 = lo[c];
        const uint32_t hw[4] = {h4.x, h4.y, h4.z, h4.w};
        const uint32_t lw[4] = {l4.x, l4.y, l4.z, l4.w};
        #pragma unroll
        for (int q = 0; q < 4; ++q) {
            const __half2 hh = *(const __half2*)&hw[q];
            const __half2 ll = *(const __half2*)&lw[q];
            const int k = c * 8 + q * 2;
            const float a0 = __half2float(__low2half(hh))  + __half2float(__low2half(ll));
            const float a1 = __half2float(__high2half(hh)) + __half2float(__high2half(ll));
            acc = fmaf(a0, W3[(size_t)k * 1024 + col], acc);
            acc = fmaf(a1, W3[(size_t)(k + 1) * 1024 + col], acc);
        }
    }
    g_G[b * 1024 + col] = fmaxf(acc + b3[col], 0.0f);
}

// ---------------------------------------------------------------------------
// Head GEMMs: C = act(A @ B + bias). 16x64 tile (2x CTAs vs R8 for SM
// coverage), cp.async double-buffered.
// ---------------------------------------------------------------------------
#define HD_AS 1088    // 16*68 floats
#define HD_BS 4096    // 64*64 floats
#define HD_STAGE (HD_AS + HD_BS)
#define HD_SMEM (2 * HD_STAGE * 4)

__device__ __forceinline__ void hd_load_chunk(
    uint32_t as, uint32_t bs,
    const float* __restrict__ A, const float* __restrict__ B,
    int rowBase, int colBase, int K, int ldb, int k0, int tid)
{
    {
        const int r = tid >> 4, k = (tid & 15) * 4;   // 256 slots, 1/thread
        CP_ASYNC16(as + (r * 68 + k) * 4, A + (size_t)(rowBase + r) * K + k0 + k);
    }
    #pragma unroll
    for (int i = 0; i < 4; ++i) {
        const int idx = tid + i * 256;
        const int r = idx >> 4, c = (idx & 15) * 4;
        CP_ASYNC16(bs + (r * 64 + c) * 4, B + (size_t)(k0 + r) * ldb + colBase + c);
    }
}

__device__ __forceinline__ void head_gemm_16(
    const float* __restrict__ A, const float* __restrict__ B,
    const float* __restrict__ bias, float* __restrict__ C,
    int K, int ldb, bool relu)
{
    float* sm = (float*)smem_raw;
    const uint32_t sb = smem_u32(sm);
    const int tid = threadIdx.x;
    const int tx = tid & 15, ty = tid >> 4;
    const int rowBase = blockIdx.x * 16;
    const int colBase = blockIdx.y * 64;
    const int nChunks = K >> 6;

    hd_load_chunk(sb, sb + HD_AS * 4, A, B, rowBase, colBase, K, ldb, 0, tid);
    CP_COMMIT();

    float acc[4] = {0.0f, 0.0f, 0.0f, 0.0f};

    for (int ch = 0; ch < nChunks; ++ch) {
        if (ch + 1 < nChunks) {
            const uint32_t as = sb + ((ch + 1) & 1) * HD_STAGE * 4;
            hd_load_chunk(as, as + HD_AS * 4, A, B, rowBase, colBase, K, ldb, (ch + 1) * 64, tid);
            CP_COMMIT();
            CP_WAIT(1);
        } else {
            CP_WAIT(0);
        }
        __syncthreads();

        const float* As = sm + (ch & 1) * HD_STAGE;
        const float* Bs = As + HD_AS;

        #pragma unroll 16
        for (int k = 0; k < 64; ++k) {
            const float4 wv = *(const float4*)(Bs + k * 64 + tx * 4);
            const float a0 = As[ty * 68 + k];
            acc[0] = fmaf(a0, wv.x, acc[0]); acc[1] = fmaf(a0, wv.y, acc[1]);
            acc[2] = fmaf(a0, wv.z, acc[2]); acc[3] = fmaf(a0, wv.w, acc[3]);
        }
        __syncthreads();
    }

    #pragma unroll
    for (int c = 0; c < 4; ++c) {
        float v = acc[c] + bias[colBase + tx * 4 + c];
        if (relu) v = fmaxf(v, 0.0f);
        C[(size_t)(rowBase + ty) * ldb + colBase + tx * 4 + c] = v;
    }
}

__global__ void k3_head1(const float* __restrict__ Wh1, const float* __restrict__ bh1) {
    head_gemm_16(g_G, Wh1, bh1, g_Z1, 1024, 512, true);
}
__global__ void k4_head2(const float* __restrict__ Wh2, const float* __restrict__ bh2) {
    head_gemm_16(g_Z1, Wh2, bh2, g_Z2, 512, 256, true);
}

// ---------------------------------------------------------------------------
// K5: raw = Z2 @ Wh3 + bh3 — warp per output, shfl reduce.
// ---------------------------------------------------------------------------
__global__ void k5_raw(const float* __restrict__ Wh3, const float* __restrict__ bh3)
{
    const int g = blockIdx.x * 8 + (threadIdx.x >> 5);
    if (g >= BATCH * 9) return;
    const int lane = threadIdx.x & 31;
    const int b = g / 9, j = g % 9;
    const float* z = g_Z2 + b * 256;
    float acc = 0.0f;
    #pragma unroll
    for (int i = 0; i < 8; ++i) {
        const int k = lane + i * 32;
        acc = fmaf(z[k], Wh3[k * 9 + j], acc);
    }
    #pragma unroll
    for (int off = 16; off > 0; off >>= 1)
        acc += __shfl_xor_sync(0xffffffffu, acc, off);
    if (lane == 0) g_RAW[g] = acc + bh3[j];
}

// ---------------------------------------------------------------------------
// K6: SVD projection onto SO(3). One thread per 3x3 matrix.
// ---------------------------------------------------------------------------
__device__ __forceinline__ void jrot(float A[3][3], float V[3][3], int p, int q)
{
    float apq = A[p][q];
    if (fabsf(apq) < 1e-20f) return;
    float tau = (A[q][q] - A[p][p]) / (2.0f * apq);
    float t = copysignf(1.0f, tau) / (fabsf(tau) + sqrtf(1.0f + tau * tau));
    float c = 1.0f / sqrtf(1.0f + t * t);
    float s = t * c;
    for (int r = 0; r < 3; ++r) {
        float arp = A[r][p], arq = A[r][q];
        A[r][p] = c * arp - s * arq;
        A[r][q] = s * arp + c * arq;
    }
    for (int r = 0; r < 3; ++r) {
        float apr = A[p][r], aqr = A[q][r];
        A[p][r] = c * apr - s * aqr;
        A[q][r] = s * apr + c * aqr;
    }
    for (int r = 0; r < 3; ++r) {
        float vrp = V[r][p], vrq = V[r][q];
        V[r][p] = c * vrp - s * vrq;
        V[r][q] = s * vrp + c * vrq;
    }
}

__global__ void k6_svd(float* __restrict__ out)
{
    int i = blockIdx.x * 32 + threadIdx.x;
    if (i >= BATCH) return;

    float M[3][3];
    for (int r = 0; r < 3; ++r)
        for (int c = 0; c < 3; ++c)
            M[r][c] = g_RAW[i * 9 + r * 3 + c];

    float A[3][3], V[3][3];
    for (int r = 0; r < 3; ++r)
        for (int c = 0; c < 3; ++c) {
            A[r][c] = M[0][r] * M[0][c] + M[1][r] * M[1][c] + M[2][r] * M[2][c];
            V[r][c] = (r == c) ? 1.0f : 0.0f;
        }

    for (int sweep = 0; sweep < 12; ++sweep) {
        jrot(A, V, 0, 1);
        jrot(A, V, 0, 2);
        jrot(A, V, 1, 2);
    }

    float e0 = A[0][0], e1 = A[1][1], e2 = A[2][2];
    int i0 = 0, i1 = 1, i2 = 2;
    if (e0 < e1) { float t = e0; e0 = e1; e1 = t; int ti = i0; i0 = i1; i1 = ti; }
    if (e0 < e2) { float t = e0; e0 = e2; e2 = t; int ti = i0; i0 = i2; i2 = ti; }
    if (e1 < e2) { float t = e1; e1 = e2; e2 = t; int ti = i1; i1 = i2; i2 = ti; }

    float v1[3], v2[3], v3[3];
    for (int r = 0; r < 3; ++r) { v1[r] = V[r][i0]; v2[r] = V[r][i1]; v3[r] = V[r][i2]; }

    float detV = v1[0] * (v2[1] * v3[2] - v2[2] * v3[1])
               - v1[1] * (v2[0] * v3[2] - v2[2] * v3[0])
               + v1[2] * (v2[0] * v3[1] - v2[1] * v3[0]);

    float w1[3], w2[3];
    for (int r = 0; r < 3; ++r) {
        w1[r] = M[r][0] * v1[0] + M[r][1] * v1[1] + M[r][2] * v1[2];
        w2[r] = M[r][0] * v2[0] + M[r][1] * v2[1] + M[r][2] * v2[2];
    }
    float n1 = sqrtf(w1[0] * w1[0] + w1[1] * w1[1] + w1[2] * w1[2] + 1e-30f);
    float u1[3] = { w1[0] / n1, w1[1] / n1, w1[2] / n1 };
    float d12 = u1[0] * w2[0] + u1[1] * w2[1] + u1[2] * w2[2];
    for (int r = 0; r < 3; ++r) w2[r] -= d12 * u1[r];
    float n2 = sqrtf(w2[0] * w2[0] + w2[1] * w2[1] + w2[2] * w2[2] + 1e-30f);
    float u2[3] = { w2[0] / n2, w2[1] / n2, w2[2] / n2 };
    float u3[3] = { u1[1] * u2[2] - u1[2] * u2[1],
                    u1[2] * u2[0] - u1[0] * u2[2],
                    u1[0] * u2[1] - u1[1] * u2[0] };
    if (detV < 0.0f) { u3[0] = -u3[0]; u3[1] = -u3[1]; u3[2] = -u3[2]; }

    for (int r = 0; r < 3; ++r)
        for (int c = 0; c < 3; ++c)
            out[i * 9 + r * 3 + c] = u1[r] * v1[c] + u2[r] * v2[c] + u3[r] * v3[c];
}

// ---------------------------------------------------------------------------
extern "C" void kernel_launch(void* const* d_in, const int* in_sizes, int n_in,
                              void* d_out, int out_size)
{
    const float* x   = (const float*)d_in[0];
    const float* W1  = (const float*)d_in[1];
    const float* b1  = (const float*)d_in[2];
    const float* W2  = (const float*)d_in[3];
    const float* b2  = (const float*)d_in[4];
    const float* W3  = (const float*)d_in[5];
    const float* b3  = (const float*)d_in[6];
    const float* Wh1 = (const float*)d_in[7];
    const float* bh1 = (const float*)d_in[8];
    const float* Wh2 = (const float*)d_in[9];
    const float* bh2 = (const float*)d_in[10];
    const float* Wh3 = (const float*)d_in[11];
    const float* bh3 = (const float*)d_in[12];
    float* out = (float*)d_out;

    cudaFuncSetAttribute(k1_point_mlp,  cudaFuncAttributeMaxDynamicSharedMemorySize, K1_SMEM);
    cudaFuncSetAttribute(k2_gemm_amax,  cudaFuncAttributeMaxDynamicSharedMemorySize, K2_SMEM);
    cudaFuncSetAttribute(k3_head1,      cudaFuncAttributeMaxDynamicSharedMemorySize, HD_SMEM);
    cudaFuncSetAttribute(k4_head2,      cudaFuncAttributeMaxDynamicSharedMemorySize, HD_SMEM);

    k1_point_mlp<<<2048, 512, K1_SMEM>>>(x, W1, b1, W2, b2);
    k2_gemm_amax<<<dim3(4, 256), 256, K2_SMEM>>>(W3);
    k2_fixup<<<dim3(4, 256), 256>>>(W3, b3);
    k3_head1<<<dim3(16, 8), 256, HD_SMEM>>>(Wh1, bh1);
    k4_head2<<<dim3(16, 4), 256, HD_SMEM>>>(Wh2, bh2);
    k5_raw<<<288, 256>>>(Wh3, bh3);
    k6_svd<<<8, 32>>>(out);

    (void)in_sizes; (void)n_in; (void)out_size;
}